// round 8
// baseline (speedup 1.0000x reference)
#include <cuda_runtime.h>
#include <cuda_bf16.h>
#include <math.h>
#include <stdint.h>

#define Ldim 2048
#define Sdim 2048
#define Nb   2
#define Ed   512
#define Hh   8
#define Dd   64

#define WOFF ((size_t)Ldim * Nb * Ed)   // offset of attn_weights in d_out

// Scratch
__device__ float g_V[(size_t)Nb * Hh * Sdim * Dd];
__device__ float g_O[(size_t)Nb * Hh * Ldim * Dd];
__device__ __nv_bfloat16 g_Qh[(size_t)Nb * Hh * Ldim * Dd];
__device__ __nv_bfloat16 g_Ql[(size_t)Nb * Hh * Ldim * Dd];
__device__ __nv_bfloat16 g_Kh[(size_t)Nb * Hh * Sdim * Dd];
__device__ __nv_bfloat16 g_Kl[(size_t)Nb * Hh * Sdim * Dd];

// ===================== mma.sync helpers (family-common PTX) =====================
__device__ __forceinline__ uint32_t smem_u32(const void* p) {
    uint32_t a;
    asm("{ .reg .u64 t; cvta.to.shared.u64 t, %1; cvt.u32.u64 %0, t; }" : "=r"(a) : "l"(p));
    return a;
}

__device__ __forceinline__ void ldsm_x4(uint32_t r[4], uint32_t addr) {
    asm volatile("ldmatrix.sync.aligned.m8n8.x4.shared.b16 {%0,%1,%2,%3}, [%4];"
                 : "=r"(r[0]), "=r"(r[1]), "=r"(r[2]), "=r"(r[3]) : "r"(addr));
}

__device__ __forceinline__ void mma_bf16(float c[4], const uint32_t a[4],
                                         uint32_t b0, uint32_t b1) {
    asm volatile("mma.sync.aligned.m16n8k16.row.col.f32.bf16.bf16.f32 "
                 "{%0,%1,%2,%3}, {%4,%5,%6,%7}, {%8,%9}, {%0,%1,%2,%3};"
                 : "+f"(c[0]), "+f"(c[1]), "+f"(c[2]), "+f"(c[3])
                 : "r"(a[0]), "r"(a[1]), "r"(a[2]), "r"(a[3]), "r"(b0), "r"(b1));
}

// ---------------------------------------------------------------------------
// fp32 projection (used for V): C[m,j] = X[m,:]·W[j,:] + b[j], scatter to
// out[n][h][t][d].
// ---------------------------------------------------------------------------
__global__ void proj_kernel(const float* __restrict__ X,
                            const float* __restrict__ W,
                            const float* __restrict__ bias,
                            float* __restrict__ out)
{
    __shared__ float As[64][33];
    __shared__ float Bs[64][33];
    const int m0 = blockIdx.y * 64;
    const int j0 = blockIdx.x * 64;
    const int tid = threadIdx.x;
    const int tx = tid & 15, ty = tid >> 4;

    float acc[4][4] = {};

    for (int kt = 0; kt < Ed; kt += 32) {
        #pragma unroll
        for (int i = 0; i < 2; ++i) {
            int idx = tid + i * 256;
            int row = idx >> 3;
            int c4  = idx & 7;
            float4 va = *(const float4*)(X + (size_t)(m0 + row) * Ed + kt + c4 * 4);
            As[row][c4*4+0] = va.x; As[row][c4*4+1] = va.y;
            As[row][c4*4+2] = va.z; As[row][c4*4+3] = va.w;
            float4 vb = *(const float4*)(W + (size_t)(j0 + row) * Ed + kt + c4 * 4);
            Bs[row][c4*4+0] = vb.x; Bs[row][c4*4+1] = vb.y;
            Bs[row][c4*4+2] = vb.z; Bs[row][c4*4+3] = vb.w;
        }
        __syncthreads();
        #pragma unroll 8
        for (int k = 0; k < 32; ++k) {
            float a0 = As[ty*4+0][k], a1 = As[ty*4+1][k];
            float a2 = As[ty*4+2][k], a3 = As[ty*4+3][k];
            float b0 = Bs[tx*4+0][k], b1 = Bs[tx*4+1][k];
            float b2 = Bs[tx*4+2][k], b3 = Bs[tx*4+3][k];
            acc[0][0] = fmaf(a0,b0,acc[0][0]); acc[0][1] = fmaf(a0,b1,acc[0][1]);
            acc[0][2] = fmaf(a0,b2,acc[0][2]); acc[0][3] = fmaf(a0,b3,acc[0][3]);
            acc[1][0] = fmaf(a1,b0,acc[1][0]); acc[1][1] = fmaf(a1,b1,acc[1][1]);
            acc[1][2] = fmaf(a1,b2,acc[1][2]); acc[1][3] = fmaf(a1,b3,acc[1][3]);
            acc[2][0] = fmaf(a2,b0,acc[2][0]); acc[2][1] = fmaf(a2,b1,acc[2][1]);
            acc[2][2] = fmaf(a2,b2,acc[2][2]); acc[2][3] = fmaf(a2,b3,acc[2][3]);
            acc[3][0] = fmaf(a3,b0,acc[3][0]); acc[3][1] = fmaf(a3,b1,acc[3][1]);
            acc[3][2] = fmaf(a3,b2,acc[3][2]); acc[3][3] = fmaf(a3,b3,acc[3][3]);
        }
        __syncthreads();
    }

    #pragma unroll
    for (int i = 0; i < 4; ++i) {
        int m = m0 + ty * 4 + i;
        int t = m >> 1;
        int n = m & 1;
        #pragma unroll
        for (int jj = 0; jj < 4; ++jj) {
            int j = j0 + tx * 4 + jj;
            int h = j >> 6, d = j & 63;
            out[(((size_t)n * Hh + h) * Ldim + t) * Dd + d] = acc[i][jj] + bias[j];
        }
    }
}

// ---------------------------------------------------------------------------
// Split projection (used for Q, K): same GEMM, writes bf16 hi + bf16 lo.
// ---------------------------------------------------------------------------
__global__ void proj_split_kernel(const float* __restrict__ X,
                                  const float* __restrict__ W,
                                  const float* __restrict__ bias,
                                  __nv_bfloat16* __restrict__ outh,
                                  __nv_bfloat16* __restrict__ outl)
{
    __shared__ float As[64][33];
    __shared__ float Bs[64][33];
    const int m0 = blockIdx.y * 64;
    const int j0 = blockIdx.x * 64;
    const int tid = threadIdx.x;
    const int tx = tid & 15, ty = tid >> 4;

    float acc[4][4] = {};

    for (int kt = 0; kt < Ed; kt += 32) {
        #pragma unroll
        for (int i = 0; i < 2; ++i) {
            int idx = tid + i * 256;
            int row = idx >> 3;
            int c4  = idx & 7;
            float4 va = *(const float4*)(X + (size_t)(m0 + row) * Ed + kt + c4 * 4);
            As[row][c4*4+0] = va.x; As[row][c4*4+1] = va.y;
            As[row][c4*4+2] = va.z; As[row][c4*4+3] = va.w;
            float4 vb = *(const float4*)(W + (size_t)(j0 + row) * Ed + kt + c4 * 4);
            Bs[row][c4*4+0] = vb.x; Bs[row][c4*4+1] = vb.y;
            Bs[row][c4*4+2] = vb.z; Bs[row][c4*4+3] = vb.w;
        }
        __syncthreads();
        #pragma unroll 8
        for (int k = 0; k < 32; ++k) {
            float a0 = As[ty*4+0][k], a1 = As[ty*4+1][k];
            float a2 = As[ty*4+2][k], a3 = As[ty*4+3][k];
            float b0 = Bs[tx*4+0][k], b1 = Bs[tx*4+1][k];
            float b2 = Bs[tx*4+2][k], b3 = Bs[tx*4+3][k];
            acc[0][0] = fmaf(a0,b0,acc[0][0]); acc[0][1] = fmaf(a0,b1,acc[0][1]);
            acc[0][2] = fmaf(a0,b2,acc[0][2]); acc[0][3] = fmaf(a0,b3,acc[0][3]);
            acc[1][0] = fmaf(a1,b0,acc[1][0]); acc[1][1] = fmaf(a1,b1,acc[1][1]);
            acc[1][2] = fmaf(a1,b2,acc[1][2]); acc[1][3] = fmaf(a1,b3,acc[1][3]);
            acc[2][0] = fmaf(a2,b0,acc[2][0]); acc[2][1] = fmaf(a2,b1,acc[2][1]);
            acc[2][2] = fmaf(a2,b2,acc[2][2]); acc[2][3] = fmaf(a2,b3,acc[2][3]);
            acc[3][0] = fmaf(a3,b0,acc[3][0]); acc[3][1] = fmaf(a3,b1,acc[3][1]);
            acc[3][2] = fmaf(a3,b2,acc[3][2]); acc[3][3] = fmaf(a3,b3,acc[3][3]);
        }
        __syncthreads();
    }

    #pragma unroll
    for (int i = 0; i < 4; ++i) {
        int m = m0 + ty * 4 + i;
        int t = m >> 1;
        int n = m & 1;
        #pragma unroll
        for (int jj = 0; jj < 4; ++jj) {
            int j = j0 + tx * 4 + jj;
            int h = j >> 6, d = j & 63;
            float v = acc[i][jj] + bias[j];
            __nv_bfloat16 hi = __float2bfloat16(v);
            __nv_bfloat16 lo = __float2bfloat16(v - __bfloat162float(hi));
            size_t o = (((size_t)n * Hh + h) * Ldim + t) * Dd + d;
            outh[o] = hi;
            outl[o] = lo;
        }
    }
}

// ---------------------------------------------------------------------------
// qk via mma.sync bf16 split precision.
// Per block: 128 (L) x 128 (S) logits for one z = h*Nb + n, 256 threads.
// scores = Qh·Kh + Qh·Kl + Ql·Kh, fp32 accumulate.
// 8 warps as 4 (rows) x 2 (cols): warp tile 32 x 64.
// SMEM: 4 tiles of 128 rows x pitch-72 bf16 (144B rows -> ldmatrix conflict-free).
// ---------------------------------------------------------------------------
#define QK_PITCH 72
#define QK_TILE  (128 * QK_PITCH)                 // elements per tile
#define QK_SMEM_BYTES (4 * QK_TILE * 2)           // 73728 bytes

__global__ void __launch_bounds__(256)
qk_mma_kernel(const float* __restrict__ attn_bias, float* __restrict__ wout)
{
    extern __shared__ __nv_bfloat16 qs[];
    const int tid  = threadIdx.x;
    const int lane = tid & 31;
    const int wid  = tid >> 5;
    const int wr   = wid & 3;     // warp row (4 x 32 rows)
    const int wc   = wid >> 2;    // warp col (2 x 64 cols)
    const int s0 = blockIdx.x * 128;
    const int l0 = blockIdx.y * 128;
    const int z  = blockIdx.z;
    const int h = z / Nb, n = z % Nb;

    __nv_bfloat16* tQh = qs;
    __nv_bfloat16* tQl = qs + QK_TILE;
    __nv_bfloat16* tKh = qs + 2 * QK_TILE;
    __nv_bfloat16* tKl = qs + 3 * QK_TILE;

    // Stage tiles: 128 rows x 64 bf16 (128B) each, into pitch-72 smem.
    const size_t qoff = ((size_t)(n * Hh + h) * Ldim + l0) * Dd;
    const size_t koff = ((size_t)(n * Hh + h) * Sdim + s0) * Dd;
    {
        const uint4* srcs[4] = {
            (const uint4*)(g_Qh + qoff), (const uint4*)(g_Ql + qoff),
            (const uint4*)(g_Kh + koff), (const uint4*)(g_Kl + koff)
        };
        __nv_bfloat16* dsts[4] = { tQh, tQl, tKh, tKl };
        #pragma unroll
        for (int t = 0; t < 4; ++t) {
            const uint4* s = srcs[t];
            __nv_bfloat16* d = dsts[t];
            #pragma unroll
            for (int i = 0; i < 4; ++i) {
                int e = tid + i * 256;              // 1024 16B-chunks per tile
                int row = e >> 3, c = e & 7;
                *(uint4*)(d + row * QK_PITCH + c * 8) = s[row * 8 + c];
            }
        }
    }
    __syncthreads();

    float acc[2][8][4];
    #pragma unroll
    for (int mt = 0; mt < 2; ++mt)
        #pragma unroll
        for (int nt = 0; nt < 8; ++nt)
            #pragma unroll
            for (int e = 0; e < 4; ++e) acc[mt][nt][e] = 0.f;

    // ldmatrix lane addressing (canonical x4 pattern):
    // A: lanes 0-7 rows 0-7 (k+0), 8-15 rows 8-15 (k+0), 16-23 rows 0-7 (k+8), 24-31 rows 8-15 (k+8)
    const int arow = wr * 32 + (lane & 15);
    const int acol = (lane >> 4) * 8;
    // B: lanes 0-7 n 0-7 (k+0), 8-15 n 0-7 (k+8), 16-23 n 8-15 (k+0), 24-31 n 8-15 (k+8)
    const int brow = wc * 64 + (lane & 7) + ((lane >> 4) << 3);
    const int bcol = lane & 8;

    const uint32_t uQh = smem_u32(tQh), uQl = smem_u32(tQl);
    const uint32_t uKh = smem_u32(tKh), uKl = smem_u32(tKl);
    const uint32_t qbase[3] = { uQh, uQh, uQl };
    const uint32_t kbase[3] = { uKh, uKl, uKh };

    #pragma unroll
    for (int p = 0; p < 3; ++p) {
        const uint32_t qb = qbase[p], kb = kbase[p];
        #pragma unroll
        for (int k0 = 0; k0 < 64; k0 += 16) {
            uint32_t a[2][4];
            #pragma unroll
            for (int mt = 0; mt < 2; ++mt)
                ldsm_x4(a[mt], qb + (uint32_t)(((arow + mt * 16) * QK_PITCH) + k0 + acol) * 2);
            #pragma unroll
            for (int np = 0; np < 4; ++np) {
                uint32_t b[4];
                ldsm_x4(b, kb + (uint32_t)(((brow + np * 16) * QK_PITCH) + k0 + bcol) * 2);
                mma_bf16(acc[0][np*2+0], a[0], b[0], b[1]);
                mma_bf16(acc[0][np*2+1], a[0], b[2], b[3]);
                mma_bf16(acc[1][np*2+0], a[1], b[0], b[1]);
                mma_bf16(acc[1][np*2+1], a[1], b[2], b[3]);
            }
        }
    }

    // Epilogue: scale 1/8, add bias, store. Fragment c0,c1 -> row g; c2,c3 -> row g+8.
    const int g = lane >> 2, q = lane & 3;
    #pragma unroll
    for (int mt = 0; mt < 2; ++mt) {
        #pragma unroll
        for (int nt = 0; nt < 8; ++nt) {
            int row = l0 + wr * 32 + mt * 16 + g;
            int col = s0 + wc * 64 + nt * 8 + q * 2;
            const float* bp = attn_bias + (size_t)row * Sdim + col;
            float* op = wout + ((size_t)z * Ldim + row) * Sdim + col;
            float2 b0 = *(const float2*)bp;
            float2 b8 = *(const float2*)(bp + 8 * Sdim);
            float2 r0, r8;
            r0.x = fmaf(acc[mt][nt][0], 0.125f, b0.x);
            r0.y = fmaf(acc[mt][nt][1], 0.125f, b0.y);
            r8.x = fmaf(acc[mt][nt][2], 0.125f, b8.x);
            r8.y = fmaf(acc[mt][nt][3], 0.125f, b8.y);
            *(float2*)op = r0;
            *(float2*)(op + 8 * Sdim) = r8;
        }
    }
}

// ---------------------------------------------------------------------------
// In-place softmax over last dim (S=2048). One 256-thread block per row.
// ---------------------------------------------------------------------------
__global__ void softmax_kernel(float* __restrict__ wout)
{
    float* p = wout + (size_t)blockIdx.x * Sdim;
    const int tid = threadIdx.x;
    __shared__ float red[8];

    float x[8];
    float m = -1e30f;
    #pragma unroll
    for (int i = 0; i < 8; ++i) { x[i] = p[tid + i * 256]; m = fmaxf(m, x[i]); }

    #pragma unroll
    for (int o = 16; o; o >>= 1) m = fmaxf(m, __shfl_xor_sync(0xffffffffu, m, o));
    if ((tid & 31) == 0) red[tid >> 5] = m;
    __syncthreads();
    float mb = red[0];
    #pragma unroll
    for (int w = 1; w < 8; ++w) mb = fmaxf(mb, red[w]);
    __syncthreads();

    float s = 0.f;
    #pragma unroll
    for (int i = 0; i < 8; ++i) { x[i] = __expf(x[i] - mb); s += x[i]; }

    #pragma unroll
    for (int o = 16; o; o >>= 1) s += __shfl_xor_sync(0xffffffffu, s, o);
    if ((tid & 31) == 0) red[tid >> 5] = s;
    __syncthreads();
    float sb = 0.f;
    #pragma unroll
    for (int w = 0; w < 8; ++w) sb += red[w];

    float inv = 1.0f / sb;
    #pragma unroll
    for (int i = 0; i < 8; ++i) p[tid + i * 256] = x[i] * inv;
}

// ---------------------------------------------------------------------------
// PV: per z: O_hn[l,d] = sum_s P[z,l,s] * V_hn[s,d]. Tiles 64x64, kt=32.
// ---------------------------------------------------------------------------
__global__ void pv_kernel(const float* __restrict__ wts)
{
    __shared__ float Ps[64][33];
    __shared__ float Vs[32][65];
    const int l0 = blockIdx.x * 64;
    const int z  = blockIdx.y;
    const int h = z / Nb, n = z % Nb;
    const float* Pb = wts + (size_t)z * Ldim * Sdim;
    const float* Vb = g_V + ((size_t)n * Hh + h) * Sdim * Dd;
    const int tid = threadIdx.x;
    const int tx = tid & 15, ty = tid >> 4;

    float acc[4][4] = {};

    for (int s0 = 0; s0 < Sdim; s0 += 32) {
        #pragma unroll
        for (int i = 0; i < 2; ++i) {
            int idx = tid + i * 256;
            int row = idx >> 3;
            int c4  = idx & 7;
            float4 v = *(const float4*)(Pb + (size_t)(l0 + row) * Sdim + s0 + c4 * 4);
            Ps[row][c4*4+0] = v.x; Ps[row][c4*4+1] = v.y;
            Ps[row][c4*4+2] = v.z; Ps[row][c4*4+3] = v.w;
            int kk = idx >> 4;
            int cv = idx & 15;
            float4 w = *(const float4*)(Vb + (size_t)(s0 + kk) * Dd + cv * 4);
            Vs[kk][cv*4+0] = w.x; Vs[kk][cv*4+1] = w.y;
            Vs[kk][cv*4+2] = w.z; Vs[kk][cv*4+3] = w.w;
        }
        __syncthreads();
        #pragma unroll 8
        for (int k = 0; k < 32; ++k) {
            float a0 = Ps[ty*4+0][k], a1 = Ps[ty*4+1][k];
            float a2 = Ps[ty*4+2][k], a3 = Ps[ty*4+3][k];
            float b0 = Vs[k][tx*4+0], b1 = Vs[k][tx*4+1];
            float b2 = Vs[k][tx*4+2], b3 = Vs[k][tx*4+3];
            acc[0][0] = fmaf(a0,b0,acc[0][0]); acc[0][1] = fmaf(a0,b1,acc[0][1]);
            acc[0][2] = fmaf(a0,b2,acc[0][2]); acc[0][3] = fmaf(a0,b3,acc[0][3]);
            acc[1][0] = fmaf(a1,b0,acc[1][0]); acc[1][1] = fmaf(a1,b1,acc[1][1]);
            acc[1][2] = fmaf(a1,b2,acc[1][2]); acc[1][3] = fmaf(a1,b3,acc[1][3]);
            acc[2][0] = fmaf(a2,b0,acc[2][0]); acc[2][1] = fmaf(a2,b1,acc[2][1]);
            acc[2][2] = fmaf(a2,b2,acc[2][2]); acc[2][3] = fmaf(a2,b3,acc[2][3]);
            acc[3][0] = fmaf(a3,b0,acc[3][0]); acc[3][1] = fmaf(a3,b1,acc[3][1]);
            acc[3][2] = fmaf(a3,b2,acc[3][2]); acc[3][3] = fmaf(a3,b3,acc[3][3]);
        }
        __syncthreads();
    }

    #pragma unroll
    for (int i = 0; i < 4; ++i) {
        int l = l0 + ty * 4 + i;
        float4 r; r.x = acc[i][0]; r.y = acc[i][1]; r.z = acc[i][2]; r.w = acc[i][3];
        *(float4*)(g_O + (((size_t)n * Hh + h) * Ldim + l) * Dd + tx * 4) = r;
    }
}

// ---------------------------------------------------------------------------
// Output projection.
// ---------------------------------------------------------------------------
__global__ void oproj_kernel(const float* __restrict__ Wo,
                             const float* __restrict__ bo,
                             float* __restrict__ out)
{
    __shared__ float As[64][33];
    __shared__ float Bs[64][33];
    const int m0 = blockIdx.y * 64;
    const int j0 = blockIdx.x * 64;
    const int tid = threadIdx.x;
    const int tx = tid & 15, ty = tid >> 4;

    float acc[4][4] = {};

    for (int kt = 0; kt < Ed; kt += 32) {
        const int hsel = kt >> 6;
        const int dsel = kt & 63;
        #pragma unroll
        for (int i = 0; i < 2; ++i) {
            int idx = tid + i * 256;
            int row = idx >> 3;
            int c4  = idx & 7;
            int m = m0 + row;
            int l = m >> 1, nn = m & 1;
            float4 va = *(const float4*)(g_O +
                (((size_t)nn * Hh + hsel) * Ldim + l) * Dd + dsel + c4 * 4);
            As[row][c4*4+0] = va.x; As[row][c4*4+1] = va.y;
            As[row][c4*4+2] = va.z; As[row][c4*4+3] = va.w;
            float4 vb = *(const float4*)(Wo + (size_t)(j0 + row) * Ed + kt + c4 * 4);
            Bs[row][c4*4+0] = vb.x; Bs[row][c4*4+1] = vb.y;
            Bs[row][c4*4+2] = vb.z; Bs[row][c4*4+3] = vb.w;
        }
        __syncthreads();
        #pragma unroll 8
        for (int k = 0; k < 32; ++k) {
            float a0 = As[ty*4+0][k], a1 = As[ty*4+1][k];
            float a2 = As[ty*4+2][k], a3 = As[ty*4+3][k];
            float b0 = Bs[tx*4+0][k], b1 = Bs[tx*4+1][k];
            float b2 = Bs[tx*4+2][k], b3 = Bs[tx*4+3][k];
            acc[0][0] = fmaf(a0,b0,acc[0][0]); acc[0][1] = fmaf(a0,b1,acc[0][1]);
            acc[0][2] = fmaf(a0,b2,acc[0][2]); acc[0][3] = fmaf(a0,b3,acc[0][3]);
            acc[1][0] = fmaf(a1,b0,acc[1][0]); acc[1][1] = fmaf(a1,b1,acc[1][1]);
            acc[1][2] = fmaf(a1,b2,acc[1][2]); acc[1][3] = fmaf(a1,b3,acc[1][3]);
            acc[2][0] = fmaf(a2,b0,acc[2][0]); acc[2][1] = fmaf(a2,b1,acc[2][1]);
            acc[2][2] = fmaf(a2,b2,acc[2][2]); acc[2][3] = fmaf(a2,b3,acc[2][3]);
            acc[3][0] = fmaf(a3,b0,acc[3][0]); acc[3][1] = fmaf(a3,b1,acc[3][1]);
            acc[3][2] = fmaf(a3,b2,acc[3][2]); acc[3][3] = fmaf(a3,b3,acc[3][3]);
        }
        __syncthreads();
    }

    #pragma unroll
    for (int i = 0; i < 4; ++i) {
        int m = m0 + ty * 4 + i;
        float4 b4 = *(const float4*)(bo + j0 + tx * 4);
        float4 r;
        r.x = acc[i][0] + b4.x; r.y = acc[i][1] + b4.y;
        r.z = acc[i][2] + b4.z; r.w = acc[i][3] + b4.w;
        *(float4*)(out + (size_t)m * Ed + j0 + tx * 4) = r;
    }
}

// ---------------------------------------------------------------------------
extern "C" void kernel_launch(void* const* d_in, const int* in_sizes, int n_in,
                              void* d_out, int out_size)
{
    const float* query     = (const float*)d_in[0];
    const float* key       = (const float*)d_in[1];
    const float* value     = (const float*)d_in[2];
    const float* attn_bias = (const float*)d_in[3];
    const float* Wq = (const float*)d_in[4];
    const float* bq = (const float*)d_in[5];
    const float* Wk = (const float*)d_in[6];
    const float* bk = (const float*)d_in[7];
    const float* Wv = (const float*)d_in[8];
    const float* bv = (const float*)d_in[9];
    const float* Wo = (const float*)d_in[10];
    const float* bo = (const float*)d_in[11];

    float* out = (float*)d_out;
    float* wts = out + WOFF;

    void *pV, *pQh, *pQl, *pKh, *pKl;
    cudaGetSymbolAddress(&pV, g_V);
    cudaGetSymbolAddress(&pQh, g_Qh);
    cudaGetSymbolAddress(&pQl, g_Ql);
    cudaGetSymbolAddress(&pKh, g_Kh);
    cudaGetSymbolAddress(&pKl, g_Kl);

    cudaFuncSetAttribute(qk_mma_kernel,
                         cudaFuncAttributeMaxDynamicSharedMemorySize, QK_SMEM_BYTES);

    dim3 blk(256);
    dim3 gproj(Ed / 64, (Ldim * Nb) / 64);            // (8, 64)
    proj_split_kernel<<<gproj, blk>>>(query, Wq, bq,
                                      (__nv_bfloat16*)pQh, (__nv_bfloat16*)pQl);
    proj_split_kernel<<<gproj, blk>>>(key, Wk, bk,
                                      (__nv_bfloat16*)pKh, (__nv_bfloat16*)pKl);
    proj_kernel<<<gproj, blk>>>(value, Wv, bv, (float*)pV);

    dim3 gqk(Sdim / 128, Ldim / 128, Hh * Nb);        // (16, 16, 16)
    qk_mma_kernel<<<gqk, dim3(256), QK_SMEM_BYTES>>>(attn_bias, wts);

    softmax_kernel<<<dim3(Hh * Nb * Ldim), blk>>>(wts);   // 32768 rows

    dim3 gpv(Ldim / 64, Hh * Nb);                     // (32, 16)
    pv_kernel<<<gpv, blk>>>(wts);

    oproj_kernel<<<gproj, blk>>>(Wo, bo, out);
}

// round 9
// speedup vs baseline: 1.3263x; 1.3263x over previous
#include <cuda_runtime.h>
#include <cuda_bf16.h>
#include <math.h>
#include <stdint.h>

#define Ldim 2048
#define Sdim 2048
#define Nb   2
#define Ed   512
#define Hh   8
#define Dd   64

#define WOFF ((size_t)Ldim * Nb * Ed)   // offset of attn_weights in d_out

// Scratch (bf16 split pairs for Q, K, V; fp32 attention output per head)
__device__ float g_O[(size_t)Nb * Hh * Ldim * Dd];
__device__ __nv_bfloat16 g_Qh[(size_t)Nb * Hh * Ldim * Dd];
__device__ __nv_bfloat16 g_Ql[(size_t)Nb * Hh * Ldim * Dd];
__device__ __nv_bfloat16 g_Kh[(size_t)Nb * Hh * Sdim * Dd];
__device__ __nv_bfloat16 g_Kl[(size_t)Nb * Hh * Sdim * Dd];
__device__ __nv_bfloat16 g_Vh[(size_t)Nb * Hh * Sdim * Dd];
__device__ __nv_bfloat16 g_Vl[(size_t)Nb * Hh * Sdim * Dd];

// ===================== mma.sync helpers (family-common PTX) =====================
__device__ __forceinline__ uint32_t smem_u32(const void* p) {
    uint32_t a;
    asm("{ .reg .u64 t; cvta.to.shared.u64 t, %1; cvt.u32.u64 %0, t; }" : "=r"(a) : "l"(p));
    return a;
}

__device__ __forceinline__ void ldsm_x4(uint32_t r[4], uint32_t addr) {
    asm volatile("ldmatrix.sync.aligned.m8n8.x4.shared.b16 {%0,%1,%2,%3}, [%4];"
                 : "=r"(r[0]), "=r"(r[1]), "=r"(r[2]), "=r"(r[3]) : "r"(addr));
}

__device__ __forceinline__ void ldsm_x4_t(uint32_t r[4], uint32_t addr) {
    asm volatile("ldmatrix.sync.aligned.m8n8.x4.trans.shared.b16 {%0,%1,%2,%3}, [%4];"
                 : "=r"(r[0]), "=r"(r[1]), "=r"(r[2]), "=r"(r[3]) : "r"(addr));
}

__device__ __forceinline__ void mma_bf16(float c[4], const uint32_t a[4],
                                         uint32_t b0, uint32_t b1) {
    asm volatile("mma.sync.aligned.m16n8k16.row.col.f32.bf16.bf16.f32 "
                 "{%0,%1,%2,%3}, {%4,%5,%6,%7}, {%8,%9}, {%0,%1,%2,%3};"
                 : "+f"(c[0]), "+f"(c[1]), "+f"(c[2]), "+f"(c[3])
                 : "r"(a[0]), "r"(a[1]), "r"(a[2]), "r"(a[3]), "r"(b0), "r"(b1));
}

// ---------------------------------------------------------------------------
// Split projection (Q, K, V): C[m,j] = X[m,:]·W[j,:] + b[j], written as
// bf16 hi + bf16 lo, scattered to out[n][h][t][d].
// ---------------------------------------------------------------------------
__global__ void proj_split_kernel(const float* __restrict__ X,
                                  const float* __restrict__ W,
                                  const float* __restrict__ bias,
                                  __nv_bfloat16* __restrict__ outh,
                                  __nv_bfloat16* __restrict__ outl)
{
    __shared__ float As[64][33];
    __shared__ float Bs[64][33];
    const int m0 = blockIdx.y * 64;
    const int j0 = blockIdx.x * 64;
    const int tid = threadIdx.x;
    const int tx = tid & 15, ty = tid >> 4;

    float acc[4][4] = {};

    for (int kt = 0; kt < Ed; kt += 32) {
        #pragma unroll
        for (int i = 0; i < 2; ++i) {
            int idx = tid + i * 256;
            int row = idx >> 3;
            int c4  = idx & 7;
            float4 va = *(const float4*)(X + (size_t)(m0 + row) * Ed + kt + c4 * 4);
            As[row][c4*4+0] = va.x; As[row][c4*4+1] = va.y;
            As[row][c4*4+2] = va.z; As[row][c4*4+3] = va.w;
            float4 vb = *(const float4*)(W + (size_t)(j0 + row) * Ed + kt + c4 * 4);
            Bs[row][c4*4+0] = vb.x; Bs[row][c4*4+1] = vb.y;
            Bs[row][c4*4+2] = vb.z; Bs[row][c4*4+3] = vb.w;
        }
        __syncthreads();
        #pragma unroll 8
        for (int k = 0; k < 32; ++k) {
            float a0 = As[ty*4+0][k], a1 = As[ty*4+1][k];
            float a2 = As[ty*4+2][k], a3 = As[ty*4+3][k];
            float b0 = Bs[tx*4+0][k], b1 = Bs[tx*4+1][k];
            float b2 = Bs[tx*4+2][k], b3 = Bs[tx*4+3][k];
            acc[0][0] = fmaf(a0,b0,acc[0][0]); acc[0][1] = fmaf(a0,b1,acc[0][1]);
            acc[0][2] = fmaf(a0,b2,acc[0][2]); acc[0][3] = fmaf(a0,b3,acc[0][3]);
            acc[1][0] = fmaf(a1,b0,acc[1][0]); acc[1][1] = fmaf(a1,b1,acc[1][1]);
            acc[1][2] = fmaf(a1,b2,acc[1][2]); acc[1][3] = fmaf(a1,b3,acc[1][3]);
            acc[2][0] = fmaf(a2,b0,acc[2][0]); acc[2][1] = fmaf(a2,b1,acc[2][1]);
            acc[2][2] = fmaf(a2,b2,acc[2][2]); acc[2][3] = fmaf(a2,b3,acc[2][3]);
            acc[3][0] = fmaf(a3,b0,acc[3][0]); acc[3][1] = fmaf(a3,b1,acc[3][1]);
            acc[3][2] = fmaf(a3,b2,acc[3][2]); acc[3][3] = fmaf(a3,b3,acc[3][3]);
        }
        __syncthreads();
    }

    #pragma unroll
    for (int i = 0; i < 4; ++i) {
        int m = m0 + ty * 4 + i;
        int t = m >> 1;
        int n = m & 1;
        #pragma unroll
        for (int jj = 0; jj < 4; ++jj) {
            int j = j0 + tx * 4 + jj;
            int h = j >> 6, d = j & 63;
            float v = acc[i][jj] + bias[j];
            __nv_bfloat16 hi = __float2bfloat16(v);
            __nv_bfloat16 lo = __float2bfloat16(v - __bfloat162float(hi));
            size_t o = (((size_t)n * Hh + h) * Ldim + t) * Dd + d;
            outh[o] = hi;
            outl[o] = lo;
        }
    }
}

// ---------------------------------------------------------------------------
// qk via mma.sync bf16 split precision.
// Per block: 128 (L) x 128 (S) logits for one z = h*Nb + n, 256 threads.
// scores = Qh·Kh + Qh·Kl + Ql·Kh, fp32 accumulate.
// Epilogue stages accs in smem then writes fully-coalesced 512B rows.
// ---------------------------------------------------------------------------
#define QK_PITCH 72
#define QK_TILE  (128 * QK_PITCH)                 // elements per tile
#define QK_SMEM_BYTES (4 * QK_TILE * 2)           // 73728 bytes
#define EPI_PITCH 132                             // float staging pitch

__global__ void __launch_bounds__(256)
qk_mma_kernel(const float* __restrict__ attn_bias, float* __restrict__ wout)
{
    extern __shared__ __nv_bfloat16 qs[];
    const int tid  = threadIdx.x;
    const int lane = tid & 31;
    const int wid  = tid >> 5;
    const int wr   = wid & 3;     // warp row (4 x 32 rows)
    const int wc   = wid >> 2;    // warp col (2 x 64 cols)
    const int s0 = blockIdx.x * 128;
    const int l0 = blockIdx.y * 128;
    const int z  = blockIdx.z;
    const int h = z / Nb, n = z % Nb;

    __nv_bfloat16* tQh = qs;
    __nv_bfloat16* tQl = qs + QK_TILE;
    __nv_bfloat16* tKh = qs + 2 * QK_TILE;
    __nv_bfloat16* tKl = qs + 3 * QK_TILE;

    const size_t qoff = ((size_t)(n * Hh + h) * Ldim + l0) * Dd;
    const size_t koff = ((size_t)(n * Hh + h) * Sdim + s0) * Dd;
    {
        const uint4* srcs[4] = {
            (const uint4*)(g_Qh + qoff), (const uint4*)(g_Ql + qoff),
            (const uint4*)(g_Kh + koff), (const uint4*)(g_Kl + koff)
        };
        __nv_bfloat16* dsts[4] = { tQh, tQl, tKh, tKl };
        #pragma unroll
        for (int t = 0; t < 4; ++t) {
            const uint4* s = srcs[t];
            __nv_bfloat16* d = dsts[t];
            #pragma unroll
            for (int i = 0; i < 4; ++i) {
                int e = tid + i * 256;
                int row = e >> 3, c = e & 7;
                *(uint4*)(d + row * QK_PITCH + c * 8) = s[row * 8 + c];
            }
        }
    }
    __syncthreads();

    float acc[2][8][4];
    #pragma unroll
    for (int mt = 0; mt < 2; ++mt)
        #pragma unroll
        for (int nt = 0; nt < 8; ++nt)
            #pragma unroll
            for (int e = 0; e < 4; ++e) acc[mt][nt][e] = 0.f;

    const int arow = wr * 32 + (lane & 15);
    const int acol = (lane >> 4) * 8;
    const int brow = wc * 64 + (lane & 7) + ((lane >> 4) << 3);
    const int bcol = lane & 8;

    const uint32_t uQh = smem_u32(tQh), uQl = smem_u32(tQl);
    const uint32_t uKh = smem_u32(tKh), uKl = smem_u32(tKl);
    const uint32_t qbase[3] = { uQh, uQh, uQl };
    const uint32_t kbase[3] = { uKh, uKl, uKh };

    #pragma unroll
    for (int p = 0; p < 3; ++p) {
        const uint32_t qb = qbase[p], kb = kbase[p];
        #pragma unroll
        for (int k0 = 0; k0 < 64; k0 += 16) {
            uint32_t a[2][4];
            #pragma unroll
            for (int mt = 0; mt < 2; ++mt)
                ldsm_x4(a[mt], qb + (uint32_t)(((arow + mt * 16) * QK_PITCH) + k0 + acol) * 2);
            #pragma unroll
            for (int np = 0; np < 4; ++np) {
                uint32_t b[4];
                ldsm_x4(b, kb + (uint32_t)(((brow + np * 16) * QK_PITCH) + k0 + bcol) * 2);
                mma_bf16(acc[0][np*2+0], a[0], b[0], b[1]);
                mma_bf16(acc[0][np*2+1], a[0], b[2], b[3]);
                mma_bf16(acc[1][np*2+0], a[1], b[0], b[1]);
                mma_bf16(acc[1][np*2+1], a[1], b[2], b[3]);
            }
        }
    }

    // Epilogue: stage raw accs in smem (tiles dead now), then coalesced stores.
    __syncthreads();
    float* Ss = (float*)qs;   // 128 x EPI_PITCH floats = 67584 B <= 73728 B
    const int g = lane >> 2, q = lane & 3;
    #pragma unroll
    for (int mt = 0; mt < 2; ++mt) {
        #pragma unroll
        for (int nt = 0; nt < 8; ++nt) {
            int row = wr * 32 + mt * 16 + g;
            int col = wc * 64 + nt * 8 + q * 2;
            *(float2*)(Ss + row * EPI_PITCH + col) =
                make_float2(acc[mt][nt][0], acc[mt][nt][1]);
            *(float2*)(Ss + (row + 8) * EPI_PITCH + col) =
                make_float2(acc[mt][nt][2], acc[mt][nt][3]);
        }
    }
    __syncthreads();

    #pragma unroll 4
    for (int it = 0; it < 16; ++it) {
        int row = it * 8 + wid;
        int col = lane * 4;
        float4 v = *(float4*)(Ss + row * EPI_PITCH + col);
        float4 b = *(const float4*)(attn_bias + (size_t)(l0 + row) * Sdim + s0 + col);
        float4 r;
        r.x = fmaf(v.x, 0.125f, b.x);
        r.y = fmaf(v.y, 0.125f, b.y);
        r.z = fmaf(v.z, 0.125f, b.z);
        r.w = fmaf(v.w, 0.125f, b.w);
        *(float4*)(wout + ((size_t)z * Ldim + l0 + row) * Sdim + s0 + col) = r;
    }
}

// ---------------------------------------------------------------------------
// In-place softmax over last dim (S=2048). One 256-thread block per row.
// ---------------------------------------------------------------------------
__global__ void softmax_kernel(float* __restrict__ wout)
{
    float* p = wout + (size_t)blockIdx.x * Sdim;
    const int tid = threadIdx.x;
    __shared__ float red[8];

    float x[8];
    float m = -1e30f;
    #pragma unroll
    for (int i = 0; i < 8; ++i) { x[i] = p[tid + i * 256]; m = fmaxf(m, x[i]); }

    #pragma unroll
    for (int o = 16; o; o >>= 1) m = fmaxf(m, __shfl_xor_sync(0xffffffffu, m, o));
    if ((tid & 31) == 0) red[tid >> 5] = m;
    __syncthreads();
    float mb = red[0];
    #pragma unroll
    for (int w = 1; w < 8; ++w) mb = fmaxf(mb, red[w]);
    __syncthreads();

    float s = 0.f;
    #pragma unroll
    for (int i = 0; i < 8; ++i) { x[i] = __expf(x[i] - mb); s += x[i]; }

    #pragma unroll
    for (int o = 16; o; o >>= 1) s += __shfl_xor_sync(0xffffffffu, s, o);
    if ((tid & 31) == 0) red[tid >> 5] = s;
    __syncthreads();
    float sb = 0.f;
    #pragma unroll
    for (int w = 0; w < 8; ++w) sb += red[w];

    float inv = 1.0f / sb;
    #pragma unroll
    for (int i = 0; i < 8; ++i) p[tid + i * 256] = x[i] * inv;
}

// ---------------------------------------------------------------------------
// PV via mma.sync bf16 split precision.
// Per block: 128 (L) x 64 (D) for one z, 256 threads, 8 warps (4 rows x 2 cols,
// warp tile 32x32). Loop S in chunks of 64.
// O = Ph·Vh + Ph·Vl + Pl·Vh; P split in-kernel from the fp32 weights.
// B fragments from row-major V via ldmatrix.x4.trans.
// ---------------------------------------------------------------------------
#define PV_PITCH 72
#define PV_P_TILE (128 * PV_PITCH)
#define PV_V_TILE (64 * PV_PITCH)
#define PV_SMEM_BYTES ((2 * PV_P_TILE + 2 * PV_V_TILE) * 2)   // 55296 bytes

__global__ void __launch_bounds__(256)
pv_mma_kernel(const float* __restrict__ wts)
{
    extern __shared__ __nv_bfloat16 ps[];
    const int tid  = threadIdx.x;
    const int lane = tid & 31;
    const int wid  = tid >> 5;
    const int wr   = wid & 3;     // 4 x 32 rows
    const int wc   = wid >> 2;    // 2 x 32 cols
    const int l0 = blockIdx.x * 128;
    const int z  = blockIdx.y;
    const int h = z / Nb, n = z % Nb;

    __nv_bfloat16* Ph = ps;
    __nv_bfloat16* Pl = ps + PV_P_TILE;
    __nv_bfloat16* Vh = ps + 2 * PV_P_TILE;
    __nv_bfloat16* Vl = ps + 2 * PV_P_TILE + PV_V_TILE;

    const float* Pb = wts + (size_t)z * Ldim * Sdim;
    const __nv_bfloat16* Vhb = g_Vh + (size_t)(n * Hh + h) * Sdim * Dd;
    const __nv_bfloat16* Vlb = g_Vl + (size_t)(n * Hh + h) * Sdim * Dd;

    float acc[2][4][4];
    #pragma unroll
    for (int mt = 0; mt < 2; ++mt)
        #pragma unroll
        for (int nt = 0; nt < 4; ++nt)
            #pragma unroll
            for (int e = 0; e < 4; ++e) acc[mt][nt][e] = 0.f;

    const int arow = wr * 32 + (lane & 15);
    const int acol = (lane >> 4) * 8;
    const int vkrow = (lane & 7) + ((lane >> 3) & 1) * 8;   // k-row within 16-tile
    const int vcol  = wc * 32 + (lane >> 4) * 8;

    const uint32_t uPh = smem_u32(Ph), uPl = smem_u32(Pl);
    const uint32_t uVh = smem_u32(Vh), uVl = smem_u32(Vl);

    for (int s0 = 0; s0 < Sdim; s0 += 64) {
        __syncthreads();
        // Load + split P chunk: 128 rows x 64 fp32.
        #pragma unroll
        for (int i = 0; i < 8; ++i) {
            int idx = tid + i * 256;           // 2048 float4
            int row = idx >> 4, c4 = idx & 15;
            float4 v = *(const float4*)(Pb + (size_t)(l0 + row) * Sdim + s0 + c4 * 4);
            __nv_bfloat16 h0 = __float2bfloat16(v.x);
            __nv_bfloat16 h1 = __float2bfloat16(v.y);
            __nv_bfloat16 h2 = __float2bfloat16(v.z);
            __nv_bfloat16 h3 = __float2bfloat16(v.w);
            __nv_bfloat16 e0 = __float2bfloat16(v.x - __bfloat162float(h0));
            __nv_bfloat16 e1 = __float2bfloat16(v.y - __bfloat162float(h1));
            __nv_bfloat16 e2 = __float2bfloat16(v.z - __bfloat162float(h2));
            __nv_bfloat16 e3 = __float2bfloat16(v.w - __bfloat162float(h3));
            __nv_bfloat16* dh = Ph + row * PV_PITCH + c4 * 4;
            __nv_bfloat16* dl = Pl + row * PV_PITCH + c4 * 4;
            dh[0] = h0; dh[1] = h1; dh[2] = h2; dh[3] = h3;
            dl[0] = e0; dl[1] = e1; dl[2] = e2; dl[3] = e3;
        }
        // Load V chunk: 64 rows x 64 bf16, hi and lo.
        #pragma unroll
        for (int i = 0; i < 2; ++i) {
            int idx = tid + i * 256;           // 512 uint4 per array
            int row = idx >> 3, c = idx & 7;
            *(uint4*)(Vh + row * PV_PITCH + c * 8) =
                ((const uint4*)(Vhb + (size_t)(s0 + row) * Dd))[c];
            *(uint4*)(Vl + row * PV_PITCH + c * 8) =
                ((const uint4*)(Vlb + (size_t)(s0 + row) * Dd))[c];
        }
        __syncthreads();

        #pragma unroll
        for (int k0 = 0; k0 < 64; k0 += 16) {
            uint32_t aH[2][4], aL[2][4];
            #pragma unroll
            for (int mt = 0; mt < 2; ++mt) {
                ldsm_x4(aH[mt], uPh + (uint32_t)(((arow + mt * 16) * PV_PITCH) + k0 + acol) * 2);
                ldsm_x4(aL[mt], uPl + (uint32_t)(((arow + mt * 16) * PV_PITCH) + k0 + acol) * 2);
            }
            #pragma unroll
            for (int ng = 0; ng < 2; ++ng) {
                uint32_t bH[4], bL[4];
                uint32_t voff = (uint32_t)(((k0 + vkrow) * PV_PITCH) + vcol + ng * 16) * 2;
                ldsm_x4_t(bH, uVh + voff);
                ldsm_x4_t(bL, uVl + voff);
                #pragma unroll
                for (int mt = 0; mt < 2; ++mt) {
                    mma_bf16(acc[mt][ng*2+0], aH[mt], bH[0], bH[1]);
                    mma_bf16(acc[mt][ng*2+1], aH[mt], bH[2], bH[3]);
                    mma_bf16(acc[mt][ng*2+0], aH[mt], bL[0], bL[1]);
                    mma_bf16(acc[mt][ng*2+1], aH[mt], bL[2], bL[3]);
                    mma_bf16(acc[mt][ng*2+0], aL[mt], bH[0], bH[1]);
                    mma_bf16(acc[mt][ng*2+1], aL[mt], bH[2], bH[3]);
                }
            }
        }
    }

    // Epilogue: write g_O fp32 [n][h][l][d].
    const int g = lane >> 2, q = lane & 3;
    float* Ob = g_O + (size_t)(n * Hh + h) * Ldim * Dd;
    #pragma unroll
    for (int mt = 0; mt < 2; ++mt) {
        #pragma unroll
        for (int nt = 0; nt < 4; ++nt) {
            int row = l0 + wr * 32 + mt * 16 + g;
            int col = wc * 32 + nt * 8 + q * 2;
            *(float2*)(Ob + (size_t)row * Dd + col) =
                make_float2(acc[mt][nt][0], acc[mt][nt][1]);
            *(float2*)(Ob + (size_t)(row + 8) * Dd + col) =
                make_float2(acc[mt][nt][2], acc[mt][nt][3]);
        }
    }
}

// ---------------------------------------------------------------------------
// Output projection: out[m=(l,n), j] = sum_e A[m,e] * Wo[j,e] + bo[j].
// ---------------------------------------------------------------------------
__global__ void oproj_kernel(const float* __restrict__ Wo,
                             const float* __restrict__ bo,
                             float* __restrict__ out)
{
    __shared__ float As[64][33];
    __shared__ float Bs[64][33];
    const int m0 = blockIdx.y * 64;
    const int j0 = blockIdx.x * 64;
    const int tid = threadIdx.x;
    const int tx = tid & 15, ty = tid >> 4;

    float acc[4][4] = {};

    for (int kt = 0; kt < Ed; kt += 32) {
        const int hsel = kt >> 6;
        const int dsel = kt & 63;
        #pragma unroll
        for (int i = 0; i < 2; ++i) {
            int idx = tid + i * 256;
            int row = idx >> 3;
            int c4  = idx & 7;
            int m = m0 + row;
            int l = m >> 1, nn = m & 1;
            float4 va = *(const float4*)(g_O +
                (((size_t)nn * Hh + hsel) * Ldim + l) * Dd + dsel + c4 * 4);
            As[row][c4*4+0] = va.x; As[row][c4*4+1] = va.y;
            As[row][c4*4+2] = va.z; As[row][c4*4+3] = va.w;
            float4 vb = *(const float4*)(Wo + (size_t)(j0 + row) * Ed + kt + c4 * 4);
            Bs[row][c4*4+0] = vb.x; Bs[row][c4*4+1] = vb.y;
            Bs[row][c4*4+2] = vb.z; Bs[row][c4*4+3] = vb.w;
        }
        __syncthreads();
        #pragma unroll 8
        for (int k = 0; k < 32; ++k) {
            float a0 = As[ty*4+0][k], a1 = As[ty*4+1][k];
            float a2 = As[ty*4+2][k], a3 = As[ty*4+3][k];
            float b0 = Bs[tx*4+0][k], b1 = Bs[tx*4+1][k];
            float b2 = Bs[tx*4+2][k], b3 = Bs[tx*4+3][k];
            acc[0][0] = fmaf(a0,b0,acc[0][0]); acc[0][1] = fmaf(a0,b1,acc[0][1]);
            acc[0][2] = fmaf(a0,b2,acc[0][2]); acc[0][3] = fmaf(a0,b3,acc[0][3]);
            acc[1][0] = fmaf(a1,b0,acc[1][0]); acc[1][1] = fmaf(a1,b1,acc[1][1]);
            acc[1][2] = fmaf(a1,b2,acc[1][2]); acc[1][3] = fmaf(a1,b3,acc[1][3]);
            acc[2][0] = fmaf(a2,b0,acc[2][0]); acc[2][1] = fmaf(a2,b1,acc[2][1]);
            acc[2][2] = fmaf(a2,b2,acc[2][2]); acc[2][3] = fmaf(a2,b3,acc[2][3]);
            acc[3][0] = fmaf(a3,b0,acc[3][0]); acc[3][1] = fmaf(a3,b1,acc[3][1]);
            acc[3][2] = fmaf(a3,b2,acc[3][2]); acc[3][3] = fmaf(a3,b3,acc[3][3]);
        }
        __syncthreads();
    }

    #pragma unroll
    for (int i = 0; i < 4; ++i) {
        int m = m0 + ty * 4 + i;
        float4 b4 = *(const float4*)(bo + j0 + tx * 4);
        float4 r;
        r.x = acc[i][0] + b4.x; r.y = acc[i][1] + b4.y;
        r.z = acc[i][2] + b4.z; r.w = acc[i][3] + b4.w;
        *(float4*)(out + (size_t)m * Ed + j0 + tx * 4) = r;
    }
}

// ---------------------------------------------------------------------------
extern "C" void kernel_launch(void* const* d_in, const int* in_sizes, int n_in,
                              void* d_out, int out_size)
{
    const float* query     = (const float*)d_in[0];
    const float* key       = (const float*)d_in[1];
    const float* value     = (const float*)d_in[2];
    const float* attn_bias = (const float*)d_in[3];
    const float* Wq = (const float*)d_in[4];
    const float* bq = (const float*)d_in[5];
    const float* Wk = (const float*)d_in[6];
    const float* bk = (const float*)d_in[7];
    const float* Wv = (const float*)d_in[8];
    const float* bv = (const float*)d_in[9];
    const float* Wo = (const float*)d_in[10];
    const float* bo = (const float*)d_in[11];

    float* out = (float*)d_out;
    float* wts = out + WOFF;

    void *pQh, *pQl, *pKh, *pKl, *pVh, *pVl;
    cudaGetSymbolAddress(&pQh, g_Qh);
    cudaGetSymbolAddress(&pQl, g_Ql);
    cudaGetSymbolAddress(&pKh, g_Kh);
    cudaGetSymbolAddress(&pKl, g_Kl);
    cudaGetSymbolAddress(&pVh, g_Vh);
    cudaGetSymbolAddress(&pVl, g_Vl);

    cudaFuncSetAttribute(qk_mma_kernel,
                         cudaFuncAttributeMaxDynamicSharedMemorySize, QK_SMEM_BYTES);
    cudaFuncSetAttribute(pv_mma_kernel,
                         cudaFuncAttributeMaxDynamicSharedMemorySize, PV_SMEM_BYTES);

    dim3 blk(256);
    dim3 gproj(Ed / 64, (Ldim * Nb) / 64);            // (8, 64)
    proj_split_kernel<<<gproj, blk>>>(query, Wq, bq,
                                      (__nv_bfloat16*)pQh, (__nv_bfloat16*)pQl);
    proj_split_kernel<<<gproj, blk>>>(key, Wk, bk,
                                      (__nv_bfloat16*)pKh, (__nv_bfloat16*)pKl);
    proj_split_kernel<<<gproj, blk>>>(value, Wv, bv,
                                      (__nv_bfloat16*)pVh, (__nv_bfloat16*)pVl);

    dim3 gqk(Sdim / 128, Ldim / 128, Hh * Nb);        // (16, 16, 16)
    qk_mma_kernel<<<gqk, dim3(256), QK_SMEM_BYTES>>>(attn_bias, wts);

    softmax_kernel<<<dim3(Hh * Nb * Ldim), blk>>>(wts);   // 32768 rows

    dim3 gpv(Ldim / 128, Hh * Nb);                    // (16, 16)
    pv_mma_kernel<<<gpv, dim3(256), PV_SMEM_BYTES>>>(wts);

    oproj_kernel<<<gproj, blk>>>(Wo, bo, out);
}

// round 15
// speedup vs baseline: 3.4719x; 2.6178x over previous
#include <cuda_runtime.h>
#include <cuda_bf16.h>
#include <math.h>
#include <stdint.h>

#define Ldim 2048
#define Sdim 2048
#define Nb   2
#define Ed   512
#define Hh   8
#define Dd   64

#define WOFF ((size_t)Ldim * Nb * Ed)   // offset of attn_weights in d_out

// Scratch
__device__ float g_O[(size_t)Nb * Hh * Ldim * Dd];
__device__ __nv_bfloat16 g_Qh[(size_t)Nb * Hh * Ldim * Dd];
__device__ __nv_bfloat16 g_Ql[(size_t)Nb * Hh * Ldim * Dd];
__device__ __nv_bfloat16 g_Kh[(size_t)Nb * Hh * Sdim * Dd];
__device__ __nv_bfloat16 g_Kl[(size_t)Nb * Hh * Sdim * Dd];
__device__ __nv_bfloat16 g_Vh[(size_t)Nb * Hh * Sdim * Dd];
__device__ __nv_bfloat16 g_Vl[(size_t)Nb * Hh * Sdim * Dd];

// ===================== mma.sync helpers =====================
__device__ __forceinline__ uint32_t smem_u32(const void* p) {
    uint32_t a;
    asm("{ .reg .u64 t; cvta.to.shared.u64 t, %1; cvt.u32.u64 %0, t; }" : "=r"(a) : "l"(p));
    return a;
}

__device__ __forceinline__ void ldsm_x4(uint32_t r[4], uint32_t addr) {
    asm volatile("ldmatrix.sync.aligned.m8n8.x4.shared.b16 {%0,%1,%2,%3}, [%4];"
                 : "=r"(r[0]), "=r"(r[1]), "=r"(r[2]), "=r"(r[3]) : "r"(addr));
}

__device__ __forceinline__ void ldsm_x4_t(uint32_t r[4], uint32_t addr) {
    asm volatile("ldmatrix.sync.aligned.m8n8.x4.trans.shared.b16 {%0,%1,%2,%3}, [%4];"
                 : "=r"(r[0]), "=r"(r[1]), "=r"(r[2]), "=r"(r[3]) : "r"(addr));
}

__device__ __forceinline__ void mma_bf16(float c[4], const uint32_t a[4],
                                         uint32_t b0, uint32_t b1) {
    asm volatile("mma.sync.aligned.m16n8k16.row.col.f32.bf16.bf16.f32 "
                 "{%0,%1,%2,%3}, {%4,%5,%6,%7}, {%8,%9}, {%0,%1,%2,%3};"
                 : "+f"(c[0]), "+f"(c[1]), "+f"(c[2]), "+f"(c[3])
                 : "r"(a[0]), "r"(a[1]), "r"(a[2]), "r"(a[3]), "r"(b0), "r"(b1));
}

#define MM_PITCH 72

// Shared 128x128 split-bf16 3-pass inner product over a 64-wide K chunk.
__device__ __forceinline__ void mma_block_3pass(
    uint32_t uAh, uint32_t uAl, uint32_t uBh, uint32_t uBl,
    int arow, int acol, int brow, int bcol, float acc[2][8][4])
{
    const uint32_t abase[3] = { uAh, uAh, uAl };
    const uint32_t bbase[3] = { uBh, uBl, uBh };
    #pragma unroll
    for (int p = 0; p < 3; ++p) {
        const uint32_t ab = abase[p], bb = bbase[p];
        #pragma unroll
        for (int k0 = 0; k0 < 64; k0 += 16) {
            uint32_t a[2][4];
            #pragma unroll
            for (int mt = 0; mt < 2; ++mt)
                ldsm_x4(a[mt], ab + (uint32_t)(((arow + mt * 16) * MM_PITCH) + k0 + acol) * 2);
            #pragma unroll
            for (int np = 0; np < 4; ++np) {
                uint32_t b[4];
                ldsm_x4(b, bb + (uint32_t)(((brow + np * 16) * MM_PITCH) + k0 + bcol) * 2);
                mma_bf16(acc[0][np*2+0], a[0], b[0], b[1]);
                mma_bf16(acc[0][np*2+1], a[0], b[2], b[3]);
                mma_bf16(acc[1][np*2+0], a[1], b[0], b[1]);
                mma_bf16(acc[1][np*2+1], a[1], b[2], b[3]);
            }
        }
    }
}

#define MM_TILE (128 * MM_PITCH)
#define MM_SMEM_BYTES (4 * MM_TILE * 2)   // 73728 bytes

// Stage a 128x64 fp32 gmem tile as split bf16 hi/lo into smem (pitch MM_PITCH).
// 128 rows x 64 floats = 2048 float4 chunks: 16 float4 per row. 256 threads.
__device__ __forceinline__ void stage_split(
    const float* src, size_t srcStride,
    __nv_bfloat16* dh, __nv_bfloat16* dl, int tid)
{
    #pragma unroll
    for (int i = 0; i < 8; ++i) {
        int idx = tid + i * 256;                // 0..2047
        int row = idx >> 4, c4 = idx & 15;      // 16 float4 per row
        float4 v = *(const float4*)(src + (size_t)row * srcStride + c4 * 4);
        __nv_bfloat16 h0 = __float2bfloat16(v.x);
        __nv_bfloat16 h1 = __float2bfloat16(v.y);
        __nv_bfloat16 h2 = __float2bfloat16(v.z);
        __nv_bfloat16 h3 = __float2bfloat16(v.w);
        __nv_bfloat16* ph = dh + row * MM_PITCH + c4 * 4;
        __nv_bfloat16* pl = dl + row * MM_PITCH + c4 * 4;
        ph[0] = h0; ph[1] = h1; ph[2] = h2; ph[3] = h3;
        pl[0] = __float2bfloat16(v.x - __bfloat162float(h0));
        pl[1] = __float2bfloat16(v.y - __bfloat162float(h1));
        pl[2] = __float2bfloat16(v.z - __bfloat162float(h2));
        pl[3] = __float2bfloat16(v.w - __bfloat162float(h3));
    }
}

// ---------------------------------------------------------------------------
// Projection via mma.sync: C[m,j] = X[m,:]·W[j,:] + b[j], m=(t,n).
// Writes split bf16 hi/lo scattered to out[n][h][t][d]. 128x128 tile, K=512.
// ---------------------------------------------------------------------------
__global__ void __launch_bounds__(256)
proj_mma_kernel(const float* __restrict__ X,
                const float* __restrict__ W,
                const float* __restrict__ bias,
                __nv_bfloat16* __restrict__ outh,
                __nv_bfloat16* __restrict__ outl)
{
    extern __shared__ __nv_bfloat16 sm[];
    __nv_bfloat16* tAh = sm;
    __nv_bfloat16* tAl = sm + MM_TILE;
    __nv_bfloat16* tBh = sm + 2 * MM_TILE;
    __nv_bfloat16* tBl = sm + 3 * MM_TILE;

    const int tid  = threadIdx.x;
    const int lane = tid & 31;
    const int wid  = tid >> 5;
    const int wr   = wid & 3;
    const int wc   = wid >> 2;
    const int m0 = blockIdx.y * 128;
    const int j0 = blockIdx.x * 128;

    float acc[2][8][4];
    #pragma unroll
    for (int mt = 0; mt < 2; ++mt)
        #pragma unroll
        for (int nt = 0; nt < 8; ++nt)
            #pragma unroll
            for (int e = 0; e < 4; ++e) acc[mt][nt][e] = 0.f;

    const int arow = wr * 32 + (lane & 15);
    const int acol = (lane >> 4) * 8;
    const int brow = wc * 64 + (lane & 7) + ((lane >> 4) << 3);
    const int bcol = lane & 8;
    const uint32_t uAh = smem_u32(tAh), uAl = smem_u32(tAl);
    const uint32_t uBh = smem_u32(tBh), uBl = smem_u32(tBl);

    for (int kt = 0; kt < Ed; kt += 64) {
        __syncthreads();
        stage_split(X + (size_t)m0 * Ed + kt, Ed, tAh, tAl, tid);
        stage_split(W + (size_t)j0 * Ed + kt, Ed, tBh, tBl, tid);
        __syncthreads();
        mma_block_3pass(uAh, uAl, uBh, uBl, arow, acol, brow, bcol, acc);
    }

    // Epilogue: add bias, split, scatter to [n][h][t][d].
    const int g = lane >> 2, q = lane & 3;
    #pragma unroll
    for (int mt = 0; mt < 2; ++mt) {
        #pragma unroll
        for (int nt = 0; nt < 8; ++nt) {
            int mrow = m0 + wr * 32 + mt * 16 + g;
            int col  = j0 + wc * 64 + nt * 8 + q * 2;
            float2 b2 = *(const float2*)(bias + col);
            int h = col >> 6, d = col & 63;
            #pragma unroll
            for (int half = 0; half < 2; ++half) {
                int m = mrow + half * 8;
                int t = m >> 1, n = m & 1;
                float v0 = acc[mt][nt][half * 2 + 0] + b2.x;
                float v1 = acc[mt][nt][half * 2 + 1] + b2.y;
                __nv_bfloat16 h0 = __float2bfloat16(v0);
                __nv_bfloat16 h1 = __float2bfloat16(v1);
                __nv_bfloat162 hv; hv.x = h0; hv.y = h1;
                __nv_bfloat162 lv;
                lv.x = __float2bfloat16(v0 - __bfloat162float(h0));
                lv.y = __float2bfloat16(v1 - __bfloat162float(h1));
                size_t o = (((size_t)n * Hh + h) * Ldim + t) * Dd + d;
                *(__nv_bfloat162*)(outh + o) = hv;
                *(__nv_bfloat162*)(outl + o) = lv;
            }
        }
    }
}

// ---------------------------------------------------------------------------
// Output projection via mma.sync: out[m=(l,n), j] = sum_e A[m,e]·Wo[j,e]+bo[j],
// A gathered from g_O[n][h][l][d] (k-chunk of 64 = exactly one head).
// ---------------------------------------------------------------------------
__global__ void __launch_bounds__(256)
oproj_mma_kernel(const float* __restrict__ Wo,
                 const float* __restrict__ bo,
                 float* __restrict__ out)
{
    extern __shared__ __nv_bfloat16 sm[];
    __nv_bfloat16* tAh = sm;
    __nv_bfloat16* tAl = sm + MM_TILE;
    __nv_bfloat16* tBh = sm + 2 * MM_TILE;
    __nv_bfloat16* tBl = sm + 3 * MM_TILE;

    const int tid  = threadIdx.x;
    const int lane = tid & 31;
    const int wid  = tid >> 5;
    const int wr   = wid & 3;
    const int wc   = wid >> 2;
    const int m0 = blockIdx.y * 128;
    const int j0 = blockIdx.x * 128;

    float acc[2][8][4];
    #pragma unroll
    for (int mt = 0; mt < 2; ++mt)
        #pragma unroll
        for (int nt = 0; nt < 8; ++nt)
            #pragma unroll
            for (int e = 0; e < 4; ++e) acc[mt][nt][e] = 0.f;

    const int arow = wr * 32 + (lane & 15);
    const int acol = (lane >> 4) * 8;
    const int brow = wc * 64 + (lane & 7) + ((lane >> 4) << 3);
    const int bcol = lane & 8;
    const uint32_t uAh = smem_u32(tAh), uAl = smem_u32(tAl);
    const uint32_t uBh = smem_u32(tBh), uBl = smem_u32(tBl);

    for (int kt = 0; kt < Ed; kt += 64) {
        __syncthreads();
        // Stage A: row m=m0+row -> l=m>>1, n=m&1; cols = head kt/64, d 0..63.
        // 2048 float4 chunks (16 per row).
        {
            const int hsel = kt >> 6;
            #pragma unroll
            for (int i = 0; i < 8; ++i) {
                int idx = tid + i * 256;
                int row = idx >> 4, c4 = idx & 15;
                int m = m0 + row;
                int l = m >> 1, nn = m & 1;
                const float* src = g_O + (((size_t)nn * Hh + hsel) * Ldim + l) * Dd + c4 * 4;
                float4 v = *(const float4*)src;
                __nv_bfloat16 h0 = __float2bfloat16(v.x);
                __nv_bfloat16 h1 = __float2bfloat16(v.y);
                __nv_bfloat16 h2 = __float2bfloat16(v.z);
                __nv_bfloat16 h3 = __float2bfloat16(v.w);
                __nv_bfloat16* ph = tAh + row * MM_PITCH + c4 * 4;
                __nv_bfloat16* pl = tAl + row * MM_PITCH + c4 * 4;
                ph[0] = h0; ph[1] = h1; ph[2] = h2; ph[3] = h3;
                pl[0] = __float2bfloat16(v.x - __bfloat162float(h0));
                pl[1] = __float2bfloat16(v.y - __bfloat162float(h1));
                pl[2] = __float2bfloat16(v.z - __bfloat162float(h2));
                pl[3] = __float2bfloat16(v.w - __bfloat162float(h3));
            }
        }
        stage_split(Wo + (size_t)j0 * Ed + kt, Ed, tBh, tBl, tid);
        __syncthreads();
        mma_block_3pass(uAh, uAl, uBh, uBl, arow, acol, brow, bcol, acc);
    }

    const int g = lane >> 2, q = lane & 3;
    #pragma unroll
    for (int mt = 0; mt < 2; ++mt) {
        #pragma unroll
        for (int nt = 0; nt < 8; ++nt) {
            int mrow = m0 + wr * 32 + mt * 16 + g;
            int col  = j0 + wc * 64 + nt * 8 + q * 2;
            float2 b2 = *(const float2*)(bo + col);
            *(float2*)(out + (size_t)mrow * Ed + col) =
                make_float2(acc[mt][nt][0] + b2.x, acc[mt][nt][1] + b2.y);
            *(float2*)(out + (size_t)(mrow + 8) * Ed + col) =
                make_float2(acc[mt][nt][2] + b2.x, acc[mt][nt][3] + b2.y);
        }
    }
}

// ---------------------------------------------------------------------------
// qk via mma.sync split precision. Epilogue: fragment-direct (R8-validated).
// ---------------------------------------------------------------------------
__global__ void __launch_bounds__(256)
qk_mma_kernel(const float* __restrict__ attn_bias, float* __restrict__ wout)
{
    extern __shared__ __nv_bfloat16 qs[];
    const int tid  = threadIdx.x;
    const int lane = tid & 31;
    const int wid  = tid >> 5;
    const int wr   = wid & 3;
    const int wc   = wid >> 2;
    const int s0 = blockIdx.x * 128;
    const int l0 = blockIdx.y * 128;
    const int z  = blockIdx.z;
    const int h = z / Nb, n = z % Nb;

    __nv_bfloat16* tQh = qs;
    __nv_bfloat16* tQl = qs + MM_TILE;
    __nv_bfloat16* tKh = qs + 2 * MM_TILE;
    __nv_bfloat16* tKl = qs + 3 * MM_TILE;

    const size_t qoff = ((size_t)(n * Hh + h) * Ldim + l0) * Dd;
    const size_t koff = ((size_t)(n * Hh + h) * Sdim + s0) * Dd;
    {
        const uint4* srcs[4] = {
            (const uint4*)(g_Qh + qoff), (const uint4*)(g_Ql + qoff),
            (const uint4*)(g_Kh + koff), (const uint4*)(g_Kl + koff)
        };
        __nv_bfloat16* dsts[4] = { tQh, tQl, tKh, tKl };
        #pragma unroll
        for (int t = 0; t < 4; ++t) {
            const uint4* s = srcs[t];
            __nv_bfloat16* d = dsts[t];
            #pragma unroll
            for (int i = 0; i < 4; ++i) {
                int e = tid + i * 256;          // 1024 uint4 = 8 per row (64 bf16)
                int row = e >> 3, c = e & 7;
                *(uint4*)(d + row * MM_PITCH + c * 8) = s[row * 8 + c];
            }
        }
    }
    __syncthreads();

    float acc[2][8][4];
    #pragma unroll
    for (int mt = 0; mt < 2; ++mt)
        #pragma unroll
        for (int nt = 0; nt < 8; ++nt)
            #pragma unroll
            for (int e = 0; e < 4; ++e) acc[mt][nt][e] = 0.f;

    const int arow = wr * 32 + (lane & 15);
    const int acol = (lane >> 4) * 8;
    const int brow = wc * 64 + (lane & 7) + ((lane >> 4) << 3);
    const int bcol = lane & 8;

    mma_block_3pass(smem_u32(tQh), smem_u32(tQl), smem_u32(tKh), smem_u32(tKl),
                    arow, acol, brow, bcol, acc);

    const int g = lane >> 2, q = lane & 3;
    #pragma unroll
    for (int mt = 0; mt < 2; ++mt) {
        #pragma unroll
        for (int nt = 0; nt < 8; ++nt) {
            int row = l0 + wr * 32 + mt * 16 + g;
            int col = s0 + wc * 64 + nt * 8 + q * 2;
            const float* bp = attn_bias + (size_t)row * Sdim + col;
            float* op = wout + ((size_t)z * Ldim + row) * Sdim + col;
            float2 b0 = *(const float2*)bp;
            float2 b8 = *(const float2*)(bp + 8 * Sdim);
            float2 r0, r8;
            r0.x = fmaf(acc[mt][nt][0], 0.125f, b0.x);
            r0.y = fmaf(acc[mt][nt][1], 0.125f, b0.y);
            r8.x = fmaf(acc[mt][nt][2], 0.125f, b8.x);
            r8.y = fmaf(acc[mt][nt][3], 0.125f, b8.y);
            *(float2*)op = r0;
            *(float2*)(op + 8 * Sdim) = r8;
        }
    }
}

// ---------------------------------------------------------------------------
// In-place softmax over last dim (S=2048). One 256-thread block per row.
// ---------------------------------------------------------------------------
__global__ void softmax_kernel(float* __restrict__ wout)
{
    float* p = wout + (size_t)blockIdx.x * Sdim;
    const int tid = threadIdx.x;
    __shared__ float red[8];

    float x[8];
    float m = -1e30f;
    #pragma unroll
    for (int i = 0; i < 8; ++i) { x[i] = p[tid + i * 256]; m = fmaxf(m, x[i]); }

    #pragma unroll
    for (int o = 16; o; o >>= 1) m = fmaxf(m, __shfl_xor_sync(0xffffffffu, m, o));
    if ((tid & 31) == 0) red[tid >> 5] = m;
    __syncthreads();
    float mb = red[0];
    #pragma unroll
    for (int w = 1; w < 8; ++w) mb = fmaxf(mb, red[w]);
    __syncthreads();

    float s = 0.f;
    #pragma unroll
    for (int i = 0; i < 8; ++i) { x[i] = __expf(x[i] - mb); s += x[i]; }

    #pragma unroll
    for (int o = 16; o; o >>= 1) s += __shfl_xor_sync(0xffffffffu, s, o);
    if ((tid & 31) == 0) red[tid >> 5] = s;
    __syncthreads();
    float sb = 0.f;
    #pragma unroll
    for (int w = 0; w < 8; ++w) sb += red[w];

    float inv = 1.0f / sb;
    #pragma unroll
    for (int i = 0; i < 8; ++i) p[tid + i * 256] = x[i] * inv;
}

// ---------------------------------------------------------------------------
// PV via mma.sync split precision (validated R9).
// ---------------------------------------------------------------------------
#define PV_P_TILE (128 * MM_PITCH)
#define PV_V_TILE (64 * MM_PITCH)
#define PV_SMEM_BYTES ((2 * PV_P_TILE + 2 * PV_V_TILE) * 2)   // 55296 bytes

__global__ void __launch_bounds__(256)
pv_mma_kernel(const float* __restrict__ wts)
{
    extern __shared__ __nv_bfloat16 ps[];
    const int tid  = threadIdx.x;
    const int lane = tid & 31;
    const int wid  = tid >> 5;
    const int wr   = wid & 3;
    const int wc   = wid >> 2;
    const int l0 = blockIdx.x * 128;
    const int z  = blockIdx.y;
    const int h = z / Nb, n = z % Nb;

    __nv_bfloat16* Ph = ps;
    __nv_bfloat16* Pl = ps + PV_P_TILE;
    __nv_bfloat16* Vh = ps + 2 * PV_P_TILE;
    __nv_bfloat16* Vl = ps + 2 * PV_P_TILE + PV_V_TILE;

    const float* Pb = wts + (size_t)z * Ldim * Sdim;
    const __nv_bfloat16* Vhb = g_Vh + (size_t)(n * Hh + h) * Sdim * Dd;
    const __nv_bfloat16* Vlb = g_Vl + (size_t)(n * Hh + h) * Sdim * Dd;

    float acc[2][4][4];
    #pragma unroll
    for (int mt = 0; mt < 2; ++mt)
        #pragma unroll
        for (int nt = 0; nt < 4; ++nt)
            #pragma unroll
            for (int e = 0; e < 4; ++e) acc[mt][nt][e] = 0.f;

    const int arow = wr * 32 + (lane & 15);
    const int acol = (lane >> 4) * 8;
    const int vkrow = (lane & 7) + ((lane >> 3) & 1) * 8;
    const int vcol  = wc * 32 + (lane >> 4) * 8;

    const uint32_t uPh = smem_u32(Ph), uPl = smem_u32(Pl);
    const uint32_t uVh = smem_u32(Vh), uVl = smem_u32(Vl);

    for (int s0 = 0; s0 < Sdim; s0 += 64) {
        __syncthreads();
        #pragma unroll
        for (int i = 0; i < 8; ++i) {
            int idx = tid + i * 256;
            int row = idx >> 4, c4 = idx & 15;
            float4 v = *(const float4*)(Pb + (size_t)(l0 + row) * Sdim + s0 + c4 * 4);
            __nv_bfloat16 h0 = __float2bfloat16(v.x);
            __nv_bfloat16 h1 = __float2bfloat16(v.y);
            __nv_bfloat16 h2 = __float2bfloat16(v.z);
            __nv_bfloat16 h3 = __float2bfloat16(v.w);
            __nv_bfloat16* dh = Ph + row * MM_PITCH + c4 * 4;
            __nv_bfloat16* dl = Pl + row * MM_PITCH + c4 * 4;
            dh[0] = h0; dh[1] = h1; dh[2] = h2; dh[3] = h3;
            dl[0] = __float2bfloat16(v.x - __bfloat162float(h0));
            dl[1] = __float2bfloat16(v.y - __bfloat162float(h1));
            dl[2] = __float2bfloat16(v.z - __bfloat162float(h2));
            dl[3] = __float2bfloat16(v.w - __bfloat162float(h3));
        }
        #pragma unroll
        for (int i = 0; i < 2; ++i) {
            int idx = tid + i * 256;
            int row = idx >> 3, c = idx & 7;
            *(uint4*)(Vh + row * MM_PITCH + c * 8) =
                ((const uint4*)(Vhb + (size_t)(s0 + row) * Dd))[c];
            *(uint4*)(Vl + row * MM_PITCH + c * 8) =
                ((const uint4*)(Vlb + (size_t)(s0 + row) * Dd))[c];
        }
        __syncthreads();

        #pragma unroll
        for (int k0 = 0; k0 < 64; k0 += 16) {
            uint32_t aH[2][4], aL[2][4];
            #pragma unroll
            for (int mt = 0; mt < 2; ++mt) {
                ldsm_x4(aH[mt], uPh + (uint32_t)(((arow + mt * 16) * MM_PITCH) + k0 + acol) * 2);
                ldsm_x4(aL[mt], uPl + (uint32_t)(((arow + mt * 16) * MM_PITCH) + k0 + acol) * 2);
            }
            #pragma unroll
            for (int ng = 0; ng < 2; ++ng) {
                uint32_t bH[4], bL[4];
                uint32_t voff = (uint32_t)(((k0 + vkrow) * MM_PITCH) + vcol + ng * 16) * 2;
                ldsm_x4_t(bH, uVh + voff);
                ldsm_x4_t(bL, uVl + voff);
                #pragma unroll
                for (int mt = 0; mt < 2; ++mt) {
                    mma_bf16(acc[mt][ng*2+0], aH[mt], bH[0], bH[1]);
                    mma_bf16(acc[mt][ng*2+1], aH[mt], bH[2], bH[3]);
                    mma_bf16(acc[mt][ng*2+0], aH[mt], bL[0], bL[1]);
                    mma_bf16(acc[mt][ng*2+1], aH[mt], bL[2], bL[3]);
                    mma_bf16(acc[mt][ng*2+0], aL[mt], bH[0], bH[1]);
                    mma_bf16(acc[mt][ng*2+1], aL[mt], bH[2], bH[3]);
                }
            }
        }
    }

    const int g = lane >> 2, q = lane & 3;
    float* Ob = g_O + (size_t)(n * Hh + h) * Ldim * Dd;
    #pragma unroll
    for (int mt = 0; mt < 2; ++mt) {
        #pragma unroll
        for (int nt = 0; nt < 4; ++nt) {
            int row = l0 + wr * 32 + mt * 16 + g;
            int col = wc * 32 + nt * 8 + q * 2;
            *(float2*)(Ob + (size_t)row * Dd + col) =
                make_float2(acc[mt][nt][0], acc[mt][nt][1]);
            *(float2*)(Ob + (size_t)(row + 8) * Dd + col) =
                make_float2(acc[mt][nt][2], acc[mt][nt][3]);
        }
    }
}

// ---------------------------------------------------------------------------
extern "C" void kernel_launch(void* const* d_in, const int* in_sizes, int n_in,
                              void* d_out, int out_size)
{
    const float* query     = (const float*)d_in[0];
    const float* key       = (const float*)d_in[1];
    const float* value     = (const float*)d_in[2];
    const float* attn_bias = (const float*)d_in[3];
    const float* Wq = (const float*)d_in[4];
    const float* bq = (const float*)d_in[5];
    const float* Wk = (const float*)d_in[6];
    const float* bk = (const float*)d_in[7];
    const float* Wv = (const float*)d_in[8];
    const float* bv = (const float*)d_in[9];
    const float* Wo = (const float*)d_in[10];
    const float* bo = (const float*)d_in[11];

    float* out = (float*)d_out;
    float* wts = out + WOFF;

    void *pQh, *pQl, *pKh, *pKl, *pVh, *pVl;
    cudaGetSymbolAddress(&pQh, g_Qh);
    cudaGetSymbolAddress(&pQl, g_Ql);
    cudaGetSymbolAddress(&pKh, g_Kh);
    cudaGetSymbolAddress(&pKl, g_Kl);
    cudaGetSymbolAddress(&pVh, g_Vh);
    cudaGetSymbolAddress(&pVl, g_Vl);

    cudaFuncSetAttribute(proj_mma_kernel,
                         cudaFuncAttributeMaxDynamicSharedMemorySize, MM_SMEM_BYTES);
    cudaFuncSetAttribute(oproj_mma_kernel,
                         cudaFuncAttributeMaxDynamicSharedMemorySize, MM_SMEM_BYTES);
    cudaFuncSetAttribute(qk_mma_kernel,
                         cudaFuncAttributeMaxDynamicSharedMemorySize, MM_SMEM_BYTES);
    cudaFuncSetAttribute(pv_mma_kernel,
                         cudaFuncAttributeMaxDynamicSharedMemorySize, PV_SMEM_BYTES);

    dim3 gmm(Ed / 128, (Ldim * Nb) / 128);            // (4, 32)
    proj_mma_kernel<<<gmm, dim3(256), MM_SMEM_BYTES>>>(query, Wq, bq,
        (__nv_bfloat16*)pQh, (__nv_bfloat16*)pQl);
    proj_mma_kernel<<<gmm, dim3(256), MM_SMEM_BYTES>>>(key, Wk, bk,
        (__nv_bfloat16*)pKh, (__nv_bfloat16*)pKl);
    proj_mma_kernel<<<gmm, dim3(256), MM_SMEM_BYTES>>>(value, Wv, bv,
        (__nv_bfloat16*)pVh, (__nv_bfloat16*)pVl);

    dim3 gqk(Sdim / 128, Ldim / 128, Hh * Nb);        // (16, 16, 16)
    qk_mma_kernel<<<gqk, dim3(256), MM_SMEM_BYTES>>>(attn_bias, wts);

    softmax_kernel<<<dim3(Hh * Nb * Ldim), dim3(256)>>>(wts);

    dim3 gpv(Ldim / 128, Hh * Nb);                    // (16, 16)
    pv_mma_kernel<<<gpv, dim3(256), PV_SMEM_BYTES>>>(wts);

    oproj_mma_kernel<<<gmm, dim3(256), MM_SMEM_BYTES>>>(Wo, bo, out);
}

// round 16
// speedup vs baseline: 3.4812x; 1.0027x over previous
#include <cuda_runtime.h>
#include <cuda_bf16.h>
#include <math.h>
#include <stdint.h>

#define Ldim 2048
#define Sdim 2048
#define Nb   2
#define Ed   512
#define Hh   8
#define Dd   64

#define WOFF ((size_t)Ldim * Nb * Ed)   // offset of attn_weights in d_out

// Scratch
__device__ float g_O[(size_t)Nb * Hh * Ldim * Dd];
__device__ __nv_bfloat16 g_Qh[(size_t)Nb * Hh * Ldim * Dd];
__device__ __nv_bfloat16 g_Ql[(size_t)Nb * Hh * Ldim * Dd];
__device__ __nv_bfloat16 g_Kh[(size_t)Nb * Hh * Sdim * Dd];
__device__ __nv_bfloat16 g_Kl[(size_t)Nb * Hh * Sdim * Dd];
__device__ __nv_bfloat16 g_Vh[(size_t)Nb * Hh * Sdim * Dd];
__device__ __nv_bfloat16 g_Vl[(size_t)Nb * Hh * Sdim * Dd];

// ===================== mma.sync helpers =====================
__device__ __forceinline__ uint32_t smem_u32(const void* p) {
    uint32_t a;
    asm("{ .reg .u64 t; cvta.to.shared.u64 t, %1; cvt.u32.u64 %0, t; }" : "=r"(a) : "l"(p));
    return a;
}

__device__ __forceinline__ void ldsm_x4(uint32_t r[4], uint32_t addr) {
    asm volatile("ldmatrix.sync.aligned.m8n8.x4.shared.b16 {%0,%1,%2,%3}, [%4];"
                 : "=r"(r[0]), "=r"(r[1]), "=r"(r[2]), "=r"(r[3]) : "r"(addr));
}

__device__ __forceinline__ void ldsm_x4_t(uint32_t r[4], uint32_t addr) {
    asm volatile("ldmatrix.sync.aligned.m8n8.x4.trans.shared.b16 {%0,%1,%2,%3}, [%4];"
                 : "=r"(r[0]), "=r"(r[1]), "=r"(r[2]), "=r"(r[3]) : "r"(addr));
}

__device__ __forceinline__ void mma_bf16(float c[4], const uint32_t a[4],
                                         uint32_t b0, uint32_t b1) {
    asm volatile("mma.sync.aligned.m16n8k16.row.col.f32.bf16.bf16.f32 "
                 "{%0,%1,%2,%3}, {%4,%5,%6,%7}, {%8,%9}, {%0,%1,%2,%3};"
                 : "+f"(c[0]), "+f"(c[1]), "+f"(c[2]), "+f"(c[3])
                 : "r"(a[0]), "r"(a[1]), "r"(a[2]), "r"(a[3]), "r"(b0), "r"(b1));
}

#define MM_PITCH 72

// Fused 128x128 split-bf16 inner product over a 64-wide K chunk.
// Loads each fragment ONCE (4 A-sets + 8 B-sets per k0) and issues the three
// split products (Ah·Bh + Ah·Bl + Al·Bh) from registers. Same mma count as the
// old 3-pass walk, 33% fewer ldmatrix.
__device__ __forceinline__ void mma_block_fused(
    uint32_t uAh, uint32_t uAl, uint32_t uBh, uint32_t uBl,
    int arow, int acol, int brow, int bcol, float acc[2][8][4])
{
    #pragma unroll
    for (int k0 = 0; k0 < 64; k0 += 16) {
        uint32_t aH[2][4], aL[2][4];
        #pragma unroll
        for (int mt = 0; mt < 2; ++mt) {
            uint32_t aoff = (uint32_t)(((arow + mt * 16) * MM_PITCH) + k0 + acol) * 2;
            ldsm_x4(aH[mt], uAh + aoff);
            ldsm_x4(aL[mt], uAl + aoff);
        }
        #pragma unroll
        for (int np = 0; np < 4; ++np) {
            uint32_t boff = (uint32_t)(((brow + np * 16) * MM_PITCH) + k0 + bcol) * 2;
            uint32_t bH[4], bL[4];
            ldsm_x4(bH, uBh + boff);
            ldsm_x4(bL, uBl + boff);
            #pragma unroll
            for (int mt = 0; mt < 2; ++mt) {
                mma_bf16(acc[mt][np*2+0], aH[mt], bH[0], bH[1]);
                mma_bf16(acc[mt][np*2+1], aH[mt], bH[2], bH[3]);
                mma_bf16(acc[mt][np*2+0], aH[mt], bL[0], bL[1]);
                mma_bf16(acc[mt][np*2+1], aH[mt], bL[2], bL[3]);
                mma_bf16(acc[mt][np*2+0], aL[mt], bH[0], bH[1]);
                mma_bf16(acc[mt][np*2+1], aL[mt], bH[2], bH[3]);
            }
        }
    }
}

#define MM_TILE (128 * MM_PITCH)
#define MM_SMEM_BYTES (4 * MM_TILE * 2)   // 73728 bytes

// Stage a 128x64 fp32 gmem tile as split bf16 hi/lo into smem (pitch MM_PITCH).
__device__ __forceinline__ void stage_split(
    const float* src, size_t srcStride,
    __nv_bfloat16* dh, __nv_bfloat16* dl, int tid)
{
    #pragma unroll
    for (int i = 0; i < 8; ++i) {
        int idx = tid + i * 256;                // 0..2047
        int row = idx >> 4, c4 = idx & 15;      // 16 float4 per row
        float4 v = *(const float4*)(src + (size_t)row * srcStride + c4 * 4);
        __nv_bfloat16 h0 = __float2bfloat16(v.x);
        __nv_bfloat16 h1 = __float2bfloat16(v.y);
        __nv_bfloat16 h2 = __float2bfloat16(v.z);
        __nv_bfloat16 h3 = __float2bfloat16(v.w);
        __nv_bfloat16* ph = dh + row * MM_PITCH + c4 * 4;
        __nv_bfloat16* pl = dl + row * MM_PITCH + c4 * 4;
        ph[0] = h0; ph[1] = h1; ph[2] = h2; ph[3] = h3;
        pl[0] = __float2bfloat16(v.x - __bfloat162float(h0));
        pl[1] = __float2bfloat16(v.y - __bfloat162float(h1));
        pl[2] = __float2bfloat16(v.z - __bfloat162float(h2));
        pl[3] = __float2bfloat16(v.w - __bfloat162float(h3));
    }
}

// ---------------------------------------------------------------------------
// Projection via mma.sync: C[m,j] = X[m,:]·W[j,:] + b[j], m=(t,n).
// ---------------------------------------------------------------------------
__global__ void __launch_bounds__(256)
proj_mma_kernel(const float* __restrict__ X,
                const float* __restrict__ W,
                const float* __restrict__ bias,
                __nv_bfloat16* __restrict__ outh,
                __nv_bfloat16* __restrict__ outl)
{
    extern __shared__ __nv_bfloat16 sm[];
    __nv_bfloat16* tAh = sm;
    __nv_bfloat16* tAl = sm + MM_TILE;
    __nv_bfloat16* tBh = sm + 2 * MM_TILE;
    __nv_bfloat16* tBl = sm + 3 * MM_TILE;

    const int tid  = threadIdx.x;
    const int lane = tid & 31;
    const int wid  = tid >> 5;
    const int wr   = wid & 3;
    const int wc   = wid >> 2;
    const int m0 = blockIdx.y * 128;
    const int j0 = blockIdx.x * 128;

    float acc[2][8][4];
    #pragma unroll
    for (int mt = 0; mt < 2; ++mt)
        #pragma unroll
        for (int nt = 0; nt < 8; ++nt)
            #pragma unroll
            for (int e = 0; e < 4; ++e) acc[mt][nt][e] = 0.f;

    const int arow = wr * 32 + (lane & 15);
    const int acol = (lane >> 4) * 8;
    const int brow = wc * 64 + (lane & 7) + ((lane >> 4) << 3);
    const int bcol = lane & 8;
    const uint32_t uAh = smem_u32(tAh), uAl = smem_u32(tAl);
    const uint32_t uBh = smem_u32(tBh), uBl = smem_u32(tBl);

    for (int kt = 0; kt < Ed; kt += 64) {
        __syncthreads();
        stage_split(X + (size_t)m0 * Ed + kt, Ed, tAh, tAl, tid);
        stage_split(W + (size_t)j0 * Ed + kt, Ed, tBh, tBl, tid);
        __syncthreads();
        mma_block_fused(uAh, uAl, uBh, uBl, arow, acol, brow, bcol, acc);
    }

    // Epilogue: add bias, split, scatter to [n][h][t][d].
    const int g = lane >> 2, q = lane & 3;
    #pragma unroll
    for (int mt = 0; mt < 2; ++mt) {
        #pragma unroll
        for (int nt = 0; nt < 8; ++nt) {
            int mrow = m0 + wr * 32 + mt * 16 + g;
            int col  = j0 + wc * 64 + nt * 8 + q * 2;
            float2 b2 = *(const float2*)(bias + col);
            int h = col >> 6, d = col & 63;
            #pragma unroll
            for (int half = 0; half < 2; ++half) {
                int m = mrow + half * 8;
                int t = m >> 1, n = m & 1;
                float v0 = acc[mt][nt][half * 2 + 0] + b2.x;
                float v1 = acc[mt][nt][half * 2 + 1] + b2.y;
                __nv_bfloat16 h0 = __float2bfloat16(v0);
                __nv_bfloat16 h1 = __float2bfloat16(v1);
                __nv_bfloat162 hv; hv.x = h0; hv.y = h1;
                __nv_bfloat162 lv;
                lv.x = __float2bfloat16(v0 - __bfloat162float(h0));
                lv.y = __float2bfloat16(v1 - __bfloat162float(h1));
                size_t o = (((size_t)n * Hh + h) * Ldim + t) * Dd + d;
                *(__nv_bfloat162*)(outh + o) = hv;
                *(__nv_bfloat162*)(outl + o) = lv;
            }
        }
    }
}

// ---------------------------------------------------------------------------
// Output projection via mma.sync.
// ---------------------------------------------------------------------------
__global__ void __launch_bounds__(256)
oproj_mma_kernel(const float* __restrict__ Wo,
                 const float* __restrict__ bo,
                 float* __restrict__ out)
{
    extern __shared__ __nv_bfloat16 sm[];
    __nv_bfloat16* tAh = sm;
    __nv_bfloat16* tAl = sm + MM_TILE;
    __nv_bfloat16* tBh = sm + 2 * MM_TILE;
    __nv_bfloat16* tBl = sm + 3 * MM_TILE;

    const int tid  = threadIdx.x;
    const int lane = tid & 31;
    const int wid  = tid >> 5;
    const int wr   = wid & 3;
    const int wc   = wid >> 2;
    const int m0 = blockIdx.y * 128;
    const int j0 = blockIdx.x * 128;

    float acc[2][8][4];
    #pragma unroll
    for (int mt = 0; mt < 2; ++mt)
        #pragma unroll
        for (int nt = 0; nt < 8; ++nt)
            #pragma unroll
            for (int e = 0; e < 4; ++e) acc[mt][nt][e] = 0.f;

    const int arow = wr * 32 + (lane & 15);
    const int acol = (lane >> 4) * 8;
    const int brow = wc * 64 + (lane & 7) + ((lane >> 4) << 3);
    const int bcol = lane & 8;
    const uint32_t uAh = smem_u32(tAh), uAl = smem_u32(tAl);
    const uint32_t uBh = smem_u32(tBh), uBl = smem_u32(tBl);

    for (int kt = 0; kt < Ed; kt += 64) {
        __syncthreads();
        {
            const int hsel = kt >> 6;
            #pragma unroll
            for (int i = 0; i < 8; ++i) {
                int idx = tid + i * 256;
                int row = idx >> 4, c4 = idx & 15;
                int m = m0 + row;
                int l = m >> 1, nn = m & 1;
                const float* src = g_O + (((size_t)nn * Hh + hsel) * Ldim + l) * Dd + c4 * 4;
                float4 v = *(const float4*)src;
                __nv_bfloat16 h0 = __float2bfloat16(v.x);
                __nv_bfloat16 h1 = __float2bfloat16(v.y);
                __nv_bfloat16 h2 = __float2bfloat16(v.z);
                __nv_bfloat16 h3 = __float2bfloat16(v.w);
                __nv_bfloat16* ph = tAh + row * MM_PITCH + c4 * 4;
                __nv_bfloat16* pl = tAl + row * MM_PITCH + c4 * 4;
                ph[0] = h0; ph[1] = h1; ph[2] = h2; ph[3] = h3;
                pl[0] = __float2bfloat16(v.x - __bfloat162float(h0));
                pl[1] = __float2bfloat16(v.y - __bfloat162float(h1));
                pl[2] = __float2bfloat16(v.z - __bfloat162float(h2));
                pl[3] = __float2bfloat16(v.w - __bfloat162float(h3));
            }
        }
        stage_split(Wo + (size_t)j0 * Ed + kt, Ed, tBh, tBl, tid);
        __syncthreads();
        mma_block_fused(uAh, uAl, uBh, uBl, arow, acol, brow, bcol, acc);
    }

    const int g = lane >> 2, q = lane & 3;
    #pragma unroll
    for (int mt = 0; mt < 2; ++mt) {
        #pragma unroll
        for (int nt = 0; nt < 8; ++nt) {
            int mrow = m0 + wr * 32 + mt * 16 + g;
            int col  = j0 + wc * 64 + nt * 8 + q * 2;
            float2 b2 = *(const float2*)(bo + col);
            *(float2*)(out + (size_t)mrow * Ed + col) =
                make_float2(acc[mt][nt][0] + b2.x, acc[mt][nt][1] + b2.y);
            *(float2*)(out + (size_t)(mrow + 8) * Ed + col) =
                make_float2(acc[mt][nt][2] + b2.x, acc[mt][nt][3] + b2.y);
        }
    }
}

// ---------------------------------------------------------------------------
// qk via mma.sync split precision. Fragment-direct epilogue (R8-validated).
// ---------------------------------------------------------------------------
__global__ void __launch_bounds__(256)
qk_mma_kernel(const float* __restrict__ attn_bias, float* __restrict__ wout)
{
    extern __shared__ __nv_bfloat16 qs[];
    const int tid  = threadIdx.x;
    const int lane = tid & 31;
    const int wid  = tid >> 5;
    const int wr   = wid & 3;
    const int wc   = wid >> 2;
    const int s0 = blockIdx.x * 128;
    const int l0 = blockIdx.y * 128;
    const int z  = blockIdx.z;
    const int h = z / Nb, n = z % Nb;

    __nv_bfloat16* tQh = qs;
    __nv_bfloat16* tQl = qs + MM_TILE;
    __nv_bfloat16* tKh = qs + 2 * MM_TILE;
    __nv_bfloat16* tKl = qs + 3 * MM_TILE;

    const size_t qoff = ((size_t)(n * Hh + h) * Ldim + l0) * Dd;
    const size_t koff = ((size_t)(n * Hh + h) * Sdim + s0) * Dd;
    {
        const uint4* srcs[4] = {
            (const uint4*)(g_Qh + qoff), (const uint4*)(g_Ql + qoff),
            (const uint4*)(g_Kh + koff), (const uint4*)(g_Kl + koff)
        };
        __nv_bfloat16* dsts[4] = { tQh, tQl, tKh, tKl };
        #pragma unroll
        for (int t = 0; t < 4; ++t) {
            const uint4* s = srcs[t];
            __nv_bfloat16* d = dsts[t];
            #pragma unroll
            for (int i = 0; i < 4; ++i) {
                int e = tid + i * 256;          // 1024 uint4 = 8 per row (64 bf16)
                int row = e >> 3, c = e & 7;
                *(uint4*)(d + row * MM_PITCH + c * 8) = s[row * 8 + c];
            }
        }
    }
    __syncthreads();

    float acc[2][8][4];
    #pragma unroll
    for (int mt = 0; mt < 2; ++mt)
        #pragma unroll
        for (int nt = 0; nt < 8; ++nt)
            #pragma unroll
            for (int e = 0; e < 4; ++e) acc[mt][nt][e] = 0.f;

    const int arow = wr * 32 + (lane & 15);
    const int acol = (lane >> 4) * 8;
    const int brow = wc * 64 + (lane & 7) + ((lane >> 4) << 3);
    const int bcol = lane & 8;

    mma_block_fused(smem_u32(tQh), smem_u32(tQl), smem_u32(tKh), smem_u32(tKl),
                    arow, acol, brow, bcol, acc);

    const int g = lane >> 2, q = lane & 3;
    #pragma unroll
    for (int mt = 0; mt < 2; ++mt) {
        #pragma unroll
        for (int nt = 0; nt < 8; ++nt) {
            int row = l0 + wr * 32 + mt * 16 + g;
            int col = s0 + wc * 64 + nt * 8 + q * 2;
            const float* bp = attn_bias + (size_t)row * Sdim + col;
            float* op = wout + ((size_t)z * Ldim + row) * Sdim + col;
            float2 b0 = *(const float2*)bp;
            float2 b8 = *(const float2*)(bp + 8 * Sdim);
            float2 r0, r8;
            r0.x = fmaf(acc[mt][nt][0], 0.125f, b0.x);
            r0.y = fmaf(acc[mt][nt][1], 0.125f, b0.y);
            r8.x = fmaf(acc[mt][nt][2], 0.125f, b8.x);
            r8.y = fmaf(acc[mt][nt][3], 0.125f, b8.y);
            *(float2*)op = r0;
            *(float2*)(op + 8 * Sdim) = r8;
        }
    }
}

// ---------------------------------------------------------------------------
// In-place softmax over last dim (S=2048). One 256-thread block per row.
// float4 loads/stores: 2 LDG.128 + 2 STG.128 per thread.
// ---------------------------------------------------------------------------
__global__ void softmax_kernel(float* __restrict__ wout)
{
    float4* p = (float4*)(wout + (size_t)blockIdx.x * Sdim);
    const int tid = threadIdx.x;
    __shared__ float red[8];

    float4 x0 = p[tid];
    float4 x1 = p[tid + 256];
    float m = fmaxf(fmaxf(fmaxf(x0.x, x0.y), fmaxf(x0.z, x0.w)),
                    fmaxf(fmaxf(x1.x, x1.y), fmaxf(x1.z, x1.w)));

    #pragma unroll
    for (int o = 16; o; o >>= 1) m = fmaxf(m, __shfl_xor_sync(0xffffffffu, m, o));
    if ((tid & 31) == 0) red[tid >> 5] = m;
    __syncthreads();
    float mb = red[0];
    #pragma unroll
    for (int w = 1; w < 8; ++w) mb = fmaxf(mb, red[w]);
    __syncthreads();

    x0.x = __expf(x0.x - mb); x0.y = __expf(x0.y - mb);
    x0.z = __expf(x0.z - mb); x0.w = __expf(x0.w - mb);
    x1.x = __expf(x1.x - mb); x1.y = __expf(x1.y - mb);
    x1.z = __expf(x1.z - mb); x1.w = __expf(x1.w - mb);
    float s = (x0.x + x0.y + x0.z + x0.w) + (x1.x + x1.y + x1.z + x1.w);

    #pragma unroll
    for (int o = 16; o; o >>= 1) s += __shfl_xor_sync(0xffffffffu, s, o);
    if ((tid & 31) == 0) red[tid >> 5] = s;
    __syncthreads();
    float sb = 0.f;
    #pragma unroll
    for (int w = 0; w < 8; ++w) sb += red[w];

    float inv = 1.0f / sb;
    x0.x *= inv; x0.y *= inv; x0.z *= inv; x0.w *= inv;
    x1.x *= inv; x1.y *= inv; x1.z *= inv; x1.w *= inv;
    p[tid] = x0;
    p[tid + 256] = x1;
}

// ---------------------------------------------------------------------------
// PV via mma.sync split precision (validated R9; already fragment-fused).
// ---------------------------------------------------------------------------
#define PV_P_TILE (128 * MM_PITCH)
#define PV_V_TILE (64 * MM_PITCH)
#define PV_SMEM_BYTES ((2 * PV_P_TILE + 2 * PV_V_TILE) * 2)   // 55296 bytes

__global__ void __launch_bounds__(256)
pv_mma_kernel(const float* __restrict__ wts)
{
    extern __shared__ __nv_bfloat16 ps[];
    const int tid  = threadIdx.x;
    const int lane = tid & 31;
    const int wid  = tid >> 5;
    const int wr   = wid & 3;
    const int wc   = wid >> 2;
    const int l0 = blockIdx.x * 128;
    const int z  = blockIdx.y;
    const int h = z / Nb, n = z % Nb;

    __nv_bfloat16* Ph = ps;
    __nv_bfloat16* Pl = ps + PV_P_TILE;
    __nv_bfloat16* Vh = ps + 2 * PV_P_TILE;
    __nv_bfloat16* Vl = ps + 2 * PV_P_TILE + PV_V_TILE;

    const float* Pb = wts + (size_t)z * Ldim * Sdim;
    const __nv_bfloat16* Vhb = g_Vh + (size_t)(n * Hh + h) * Sdim * Dd;
    const __nv_bfloat16* Vlb = g_Vl + (size_t)(n * Hh + h) * Sdim * Dd;

    float acc[2][4][4];
    #pragma unroll
    for (int mt = 0; mt < 2; ++mt)
        #pragma unroll
        for (int nt = 0; nt < 4; ++nt)
            #pragma unroll
            for (int e = 0; e < 4; ++e) acc[mt][nt][e] = 0.f;

    const int arow = wr * 32 + (lane & 15);
    const int acol = (lane >> 4) * 8;
    const int vkrow = (lane & 7) + ((lane >> 3) & 1) * 8;
    const int vcol  = wc * 32 + (lane >> 4) * 8;

    const uint32_t uPh = smem_u32(Ph), uPl = smem_u32(Pl);
    const uint32_t uVh = smem_u32(Vh), uVl = smem_u32(Vl);

    for (int s0 = 0; s0 < Sdim; s0 += 64) {
        __syncthreads();
        #pragma unroll
        for (int i = 0; i < 8; ++i) {
            int idx = tid + i * 256;
            int row = idx >> 4, c4 = idx & 15;
            float4 v = *(const float4*)(Pb + (size_t)(l0 + row) * Sdim + s0 + c4 * 4);
            __nv_bfloat16 h0 = __float2bfloat16(v.x);
            __nv_bfloat16 h1 = __float2bfloat16(v.y);
            __nv_bfloat16 h2 = __float2bfloat16(v.z);
            __nv_bfloat16 h3 = __float2bfloat16(v.w);
            __nv_bfloat16* dh = Ph + row * MM_PITCH + c4 * 4;
            __nv_bfloat16* dl = Pl + row * MM_PITCH + c4 * 4;
            dh[0] = h0; dh[1] = h1; dh[2] = h2; dh[3] = h3;
            dl[0] = __float2bfloat16(v.x - __bfloat162float(h0));
            dl[1] = __float2bfloat16(v.y - __bfloat162float(h1));
            dl[2] = __float2bfloat16(v.z - __bfloat162float(h2));
            dl[3] = __float2bfloat16(v.w - __bfloat162float(h3));
        }
        #pragma unroll
        for (int i = 0; i < 2; ++i) {
            int idx = tid + i * 256;
            int row = idx >> 3, c = idx & 7;
            *(uint4*)(Vh + row * MM_PITCH + c * 8) =
                ((const uint4*)(Vhb + (size_t)(s0 + row) * Dd))[c];
            *(uint4*)(Vl + row * MM_PITCH + c * 8) =
                ((const uint4*)(Vlb + (size_t)(s0 + row) * Dd))[c];
        }
        __syncthreads();

        #pragma unroll
        for (int k0 = 0; k0 < 64; k0 += 16) {
            uint32_t aH[2][4], aL[2][4];
            #pragma unroll
            for (int mt = 0; mt < 2; ++mt) {
                ldsm_x4(aH[mt], uPh + (uint32_t)(((arow + mt * 16) * MM_PITCH) + k0 + acol) * 2);
                ldsm_x4(aL[mt], uPl + (uint32_t)(((arow + mt * 16) * MM_PITCH) + k0 + acol) * 2);
            }
            #pragma unroll
            for (int ng = 0; ng < 2; ++ng) {
                uint32_t bH[4], bL[4];
                uint32_t voff = (uint32_t)(((k0 + vkrow) * MM_PITCH) + vcol + ng * 16) * 2;
                ldsm_x4_t(bH, uVh + voff);
                ldsm_x4_t(bL, uVl + voff);
                #pragma unroll
                for (int mt = 0; mt < 2; ++mt) {
                    mma_bf16(acc[mt][ng*2+0], aH[mt], bH[0], bH[1]);
                    mma_bf16(acc[mt][ng*2+1], aH[mt], bH[2], bH[3]);
                    mma_bf16(acc[mt][ng*2+0], aH[mt], bL[0], bL[1]);
                    mma_bf16(acc[mt][ng*2+1], aH[mt], bL[2], bL[3]);
                    mma_bf16(acc[mt][ng*2+0], aL[mt], bH[0], bH[1]);
                    mma_bf16(acc[mt][ng*2+1], aL[mt], bH[2], bH[3]);
                }
            }
        }
    }

    const int g = lane >> 2, q = lane & 3;
    float* Ob = g_O + (size_t)(n * Hh + h) * Ldim * Dd;
    #pragma unroll
    for (int mt = 0; mt < 2; ++mt) {
        #pragma unroll
        for (int nt = 0; nt < 4; ++nt) {
            int row = l0 + wr * 32 + mt * 16 + g;
            int col = wc * 32 + nt * 8 + q * 2;
            *(float2*)(Ob + (size_t)row * Dd + col) =
                make_float2(acc[mt][nt][0], acc[mt][nt][1]);
            *(float2*)(Ob + (size_t)(row + 8) * Dd + col) =
                make_float2(acc[mt][nt][2], acc[mt][nt][3]);
        }
    }
}

// ---------------------------------------------------------------------------
extern "C" void kernel_launch(void* const* d_in, const int* in_sizes, int n_in,
                              void* d_out, int out_size)
{
    const float* query     = (const float*)d_in[0];
    const float* key       = (const float*)d_in[1];
    const float* value     = (const float*)d_in[2];
    const float* attn_bias = (const float*)d_in[3];
    const float* Wq = (const float*)d_in[4];
    const float* bq = (const float*)d_in[5];
    const float* Wk = (const float*)d_in[6];
    const float* bk = (const float*)d_in[7];
    const float* Wv = (const float*)d_in[8];
    const float* bv = (const float*)d_in[9];
    const float* Wo = (const float*)d_in[10];
    const float* bo = (const float*)d_in[11];

    float* out = (float*)d_out;
    float* wts = out + WOFF;

    void *pQh, *pQl, *pKh, *pKl, *pVh, *pVl;
    cudaGetSymbolAddress(&pQh, g_Qh);
    cudaGetSymbolAddress(&pQl, g_Ql);
    cudaGetSymbolAddress(&pKh, g_Kh);
    cudaGetSymbolAddress(&pKl, g_Kl);
    cudaGetSymbolAddress(&pVh, g_Vh);
    cudaGetSymbolAddress(&pVl, g_Vl);

    cudaFuncSetAttribute(proj_mma_kernel,
                         cudaFuncAttributeMaxDynamicSharedMemorySize, MM_SMEM_BYTES);
    cudaFuncSetAttribute(oproj_mma_kernel,
                         cudaFuncAttributeMaxDynamicSharedMemorySize, MM_SMEM_BYTES);
    cudaFuncSetAttribute(qk_mma_kernel,
                         cudaFuncAttributeMaxDynamicSharedMemorySize, MM_SMEM_BYTES);
    cudaFuncSetAttribute(pv_mma_kernel,
                         cudaFuncAttributeMaxDynamicSharedMemorySize, PV_SMEM_BYTES);

    dim3 gmm(Ed / 128, (Ldim * Nb) / 128);            // (4, 32)
    proj_mma_kernel<<<gmm, dim3(256), MM_SMEM_BYTES>>>(query, Wq, bq,
        (__nv_bfloat16*)pQh, (__nv_bfloat16*)pQl);
    proj_mma_kernel<<<gmm, dim3(256), MM_SMEM_BYTES>>>(key, Wk, bk,
        (__nv_bfloat16*)pKh, (__nv_bfloat16*)pKl);
    proj_mma_kernel<<<gmm, dim3(256), MM_SMEM_BYTES>>>(value, Wv, bv,
        (__nv_bfloat16*)pVh, (__nv_bfloat16*)pVl);

    dim3 gqk(Sdim / 128, Ldim / 128, Hh * Nb);        // (16, 16, 16)
    qk_mma_kernel<<<gqk, dim3(256), MM_SMEM_BYTES>>>(attn_bias, wts);

    softmax_kernel<<<dim3(Hh * Nb * Ldim), dim3(256)>>>(wts);

    dim3 gpv(Ldim / 128, Hh * Nb);                    // (16, 16)
    pv_mma_kernel<<<gpv, dim3(256), PV_SMEM_BYTES>>>(wts);

    oproj_mma_kernel<<<gmm, dim3(256), MM_SMEM_BYTES>>>(Wo, bo, out);
}